// round 14
// baseline (speedup 1.0000x reference)
#include <cuda_runtime.h>
#include <cuda_bf16.h>
#include <cuda_fp16.h>
#include <math.h>

#define B_ 2
#define C3_ 128
#define DZ_ 32
#define HW_ 576
#define C2_ 96
#define K_ 8
#define E_ 256
#define NH_ 4
#define HD_ 64
#define TOPO_ 64
#define LN_EPS 1e-5f
#define LOG2E_ 1.4426950408889634f
#define ONESH 0x3C003C00u   // fp16 {1.0, 1.0}

// ------------------------- device scratch (no allocation) -------------------
__device__ float g_w1t[C2_ * 9 * TOPO_];
__device__ float g_h[B_ * K_ * HW_ * TOPO_];
__device__ float g_topo[B_ * K_ * HW_];
__device__ __nv_bfloat16 g_Q[B_ * NH_ * DZ_ * HW_ * HD_];   // pre-scaled by log2e/8
__device__ __nv_bfloat16 g_K[B_ * NH_ * K_ * HW_ * HD_];    // (b,h,c,p,d)
__device__ __half g_Vt[B_ * NH_ * K_ * HD_ * HW_];          // (b,h,c,d,p) fp16, transposed
__device__ float g_O[B_ * DZ_ * HW_ * E_];
__device__ float g_WqT[E_ * C3_];
__device__ float g_WpT[C3_ * E_];
__device__ float g_WkT[E_ * C2_];
__device__ float g_WvT[E_ * C2_];

__device__ __forceinline__ int flex_int(const void* p, int dflt) {
    int v = *(const int*)p;
    if (v >= 1 && v <= 1000000) return v;
    float f = *(const float*)p;
    if (f >= 1.f && f <= 1000000.f) return (int)f;
    return dflt;
}

__device__ __forceinline__ unsigned pk2(float lo, float hi) {          // bf16x2
    unsigned r;
    asm("cvt.rn.bf16x2.f32 %0, %1, %2;" : "=r"(r) : "f"(hi), "f"(lo));
    return r;
}

__device__ __forceinline__ unsigned pkh(float lo, float hi) {          // f16x2
    unsigned r;
    asm("cvt.rn.f16x2.f32 %0, %1, %2;" : "=r"(r) : "f"(hi), "f"(lo));
    return r;
}

__device__ __forceinline__ unsigned ex2h(unsigned x) {                 // exp2 on f16x2
    unsigned y;
    asm("ex2.approx.f16x2 %0, %1;" : "=r"(y) : "r"(x));
    return y;
}

__device__ __forceinline__ void ldsm4(unsigned& r0, unsigned& r1,
                                      unsigned& r2, unsigned& r3, unsigned addr) {
    asm volatile("ldmatrix.sync.aligned.m8n8.x4.shared.b16 {%0,%1,%2,%3}, [%4];"
                 : "=r"(r0), "=r"(r1), "=r"(r2), "=r"(r3) : "r"(addr));
}

__device__ __forceinline__ void mma_tf32(float4& d,
                                         unsigned a0, unsigned a1, unsigned a2, unsigned a3,
                                         unsigned b0, unsigned b1) {
    asm volatile(
        "mma.sync.aligned.m16n8k8.row.col.f32.tf32.tf32.f32 "
        "{%0,%1,%2,%3}, {%4,%5,%6,%7}, {%8,%9}, {%0,%1,%2,%3};"
        : "+f"(d.x), "+f"(d.y), "+f"(d.z), "+f"(d.w)
        : "r"(a0), "r"(a1), "r"(a2), "r"(a3), "r"(b0), "r"(b1));
}

__device__ __forceinline__ void mma_bf16(float4& d,
                                         unsigned a0, unsigned a1, unsigned a2, unsigned a3,
                                         unsigned b0, unsigned b1) {
    asm volatile(
        "mma.sync.aligned.m16n8k16.row.col.f32.bf16.bf16.f32 "
        "{%0,%1,%2,%3}, {%4,%5,%6,%7}, {%8,%9}, {%0,%1,%2,%3};"
        : "+f"(d.x), "+f"(d.y), "+f"(d.z), "+f"(d.w)
        : "r"(a0), "r"(a1), "r"(a2), "r"(a3), "r"(b0), "r"(b1));
}

__device__ __forceinline__ void mma_f16(float4& d,
                                        unsigned a0, unsigned a1, unsigned a2, unsigned a3,
                                        unsigned b0, unsigned b1) {
    asm volatile(
        "mma.sync.aligned.m16n8k16.row.col.f32.f16.f16.f32 "
        "{%0,%1,%2,%3}, {%4,%5,%6,%7}, {%8,%9}, {%0,%1,%2,%3};"
        : "+f"(d.x), "+f"(d.y), "+f"(d.z), "+f"(d.w)
        : "r"(a0), "r"(a1), "r"(a2), "r"(a3), "r"(b0), "r"(b1));
}

// ------------------------- kernel 0: all weight prep ------------------------
__global__ void k_wprep(const float* __restrict__ w1,
                        const float* __restrict__ Wq, const float* __restrict__ Wp,
                        const float* __restrict__ Wk, const float* __restrict__ Wv) {
    int i = blockIdx.x * 256 + threadIdx.x;
    if (i < TOPO_ * C2_ * 9) {
        int o = i / (C2_ * 9);
        int r = i % (C2_ * 9);
        int c = r / 9, tap = r % 9;
        g_w1t[(c * 9 + tap) * TOPO_ + o] = w1[i];
    }
    if (i < C3_ * E_) {
        int e = i / C3_, c = i % C3_;
        g_WqT[i] = Wq[c * E_ + e];
        g_WpT[c * E_ + e] = Wp[i];
    }
    if (i < C2_ * E_) {
        int e = i / C2_, c = i % C2_;
        g_WkT[i] = Wk[c * E_ + e];
        g_WvT[i] = Wv[c * E_ + e];
    }
}

// ===================== fused front: conv1 | qproj | kvproj ==================
__device__ void conv1_body(int job, const float* __restrict__ F2,
                           const float* __restrict__ bng,
                           const float* __restrict__ bnb, float* sm) {
    float* in_s = sm;            // [16][6][26]
    float* w_s = sm + 2496;      // [16*9*64]
    int bk = job / 6;
    int y0 = (job % 6) * 4;
    int b = bk >> 3, k = bk & 7;
    int tid = threadIdx.x;
    int pg = tid >> 3;
    int og = tid & 7;
    int pl = pg * 3;
    int yrel = pl / 24;
    int x0 = pl % 24;
    int o0 = og * 8;
    float acc[3][8];
#pragma unroll
    for (int u = 0; u < 3; u++)
#pragma unroll
        for (int v = 0; v < 8; v++) acc[u][v] = 0.f;

    for (int c0 = 0; c0 < C2_; c0 += 16) {
        __syncthreads();
        for (int idx = tid; idx < 16 * 6 * 26; idx += 256) {
            int cc = idx / 156, rem = idx % 156;
            int yy = rem / 26, xx = rem % 26;
            int y = y0 - 1 + yy, x = xx - 1;
            float v = 0.f;
            if ((unsigned)y < 24u && (unsigned)x < 24u)
                v = F2[((b * C2_ + c0 + cc) * HW_ + y * 24 + x) * K_ + k];
            in_s[cc * 156 + yy * 26 + xx] = v;
        }
        for (int idx = tid; idx < 16 * 9 * 64; idx += 256)
            w_s[idx] = g_w1t[c0 * 9 * 64 + idx];
        __syncthreads();
        for (int cc = 0; cc < 16; cc++) {
#pragma unroll
            for (int dy = 0; dy < 3; dy++) {
                float rv[5];
#pragma unroll
                for (int u = 0; u < 5; u++) rv[u] = in_s[cc * 156 + (yrel + dy) * 26 + x0 + u];
#pragma unroll
                for (int dx = 0; dx < 3; dx++) {
                    const float* wp = &w_s[(cc * 9 + dy * 3 + dx) * 64 + o0];
                    float4 wa = *(const float4*)wp;
                    float4 wb = *(const float4*)(wp + 4);
#pragma unroll
                    for (int u = 0; u < 3; u++) {
                        float a = rv[u + dx];
                        acc[u][0] += a * wa.x; acc[u][1] += a * wa.y;
                        acc[u][2] += a * wa.z; acc[u][3] += a * wa.w;
                        acc[u][4] += a * wb.x; acc[u][5] += a * wb.y;
                        acc[u][6] += a * wb.z; acc[u][7] += a * wb.w;
                    }
                }
            }
        }
    }
    float invs = rsqrtf(1.f + LN_EPS);
    float sg[8], sb[8];
#pragma unroll
    for (int v = 0; v < 8; v++) { sg[v] = bng[o0 + v] * invs; sb[v] = bnb[o0 + v]; }
#pragma unroll
    for (int u = 0; u < 3; u++) {
        int p = (y0 + yrel) * 24 + x0 + u;
        float4 h0, h1;
        h0.x = fmaxf(acc[u][0] * sg[0] + sb[0], 0.f);
        h0.y = fmaxf(acc[u][1] * sg[1] + sb[1], 0.f);
        h0.z = fmaxf(acc[u][2] * sg[2] + sb[2], 0.f);
        h0.w = fmaxf(acc[u][3] * sg[3] + sb[3], 0.f);
        h1.x = fmaxf(acc[u][4] * sg[4] + sb[4], 0.f);
        h1.y = fmaxf(acc[u][5] * sg[5] + sb[5], 0.f);
        h1.z = fmaxf(acc[u][6] * sg[6] + sb[6], 0.f);
        h1.w = fmaxf(acc[u][7] * sg[7] + sb[7], 0.f);
        *(float4*)&g_h[(bk * HW_ + p) * TOPO_ + o0] = h0;
        *(float4*)&g_h[(bk * HW_ + p) * TOPO_ + o0 + 4] = h1;
    }
}

__device__ void qproj_body(int job, const float* __restrict__ F3,
                           const float* __restrict__ lng,
                           const float* __restrict__ lnb, float* qsm) {
    float* xk = qsm;                  // [128][72]
    float* bs = qsm + 128 * 72;       // [256][33]
    float* s_o = qsm;                 // alias, [64][260]
    __shared__ float smean[64], srstd[64];

    int p0 = (job % 9) * 64;
    int z = (job / 9) % DZ_;
    int b = job / (9 * DZ_);

    int tid = threadIdx.x;
    int w = tid >> 5, lane = tid & 31;
    int g = lane >> 2, t = lane & 3;
    int mt = w & 3, nh = w >> 2;

    {
        int r = tid & 63;
        int cb = tid >> 6;
        for (int c = cb; c < C3_; c += 4)
            xk[c * 72 + r] = F3[(b * C3_ + c) * (DZ_ * HW_) + z * HW_ + p0 + r];
    }

    float4 acc[16];
#pragma unroll
    for (int n = 0; n < 16; n++) acc[n] = make_float4(0.f, 0.f, 0.f, 0.f);

    for (int kb = 0; kb < 4; kb++) {
        __syncthreads();
        {
            int kk = tid & 31;
            int n0 = tid >> 5;
            for (int n = n0; n < 256; n += 8)
                bs[n * 33 + kk] = g_WqT[n * C3_ + kb * 32 + kk];
        }
        __syncthreads();
#pragma unroll
        for (int kcl = 0; kcl < 4; kcl++) {
            int krow = kb * 32 + kcl * 8;
            int arow = mt * 16 + g;
            unsigned a0 = __float_as_uint(xk[(krow + t) * 72 + arow]);
            unsigned a1 = __float_as_uint(xk[(krow + t) * 72 + arow + 8]);
            unsigned a2 = __float_as_uint(xk[(krow + t + 4) * 72 + arow]);
            unsigned a3 = __float_as_uint(xk[(krow + t + 4) * 72 + arow + 8]);
#pragma unroll
            for (int n = 0; n < 16; n++) {
                const float* br = &bs[(nh * 128 + n * 8 + g) * 33 + kcl * 8];
                mma_tf32(acc[n], a0, a1, a2, a3,
                         __float_as_uint(br[t]), __float_as_uint(br[t + 4]));
            }
        }
    }
    __syncthreads();

    {
        int rl = mt * 16 + g;
#pragma unroll
        for (int n = 0; n < 16; n++) {
            int col = nh * 128 + n * 8 + 2 * t;
            s_o[rl * 260 + col] = acc[n].x;
            s_o[rl * 260 + col + 1] = acc[n].y;
            s_o[(rl + 8) * 260 + col] = acc[n].z;
            s_o[(rl + 8) * 260 + col + 1] = acc[n].w;
        }
    }
    __syncthreads();

#pragma unroll
    for (int rr = 0; rr < 8; rr++) {
        int row = w * 8 + rr;
        float s = 0.f, q = 0.f;
#pragma unroll
        for (int jj = 0; jj < 8; jj++) {
            float v = s_o[row * 260 + lane + 32 * jj];
            s += v; q += v * v;
        }
#pragma unroll
        for (int off = 16; off >= 1; off >>= 1) {
            s += __shfl_xor_sync(0xffffffffu, s, off);
            q += __shfl_xor_sync(0xffffffffu, q, off);
        }
        if (lane == 0) {
            float mu = s * (1.f / 256.f);
            smean[row] = mu;
            srstd[row] = rsqrtf(q * (1.f / 256.f) - mu * mu + LN_EPS);
        }
    }
    __syncthreads();

    {
        int cl = (tid & 63) * 4;
        int rb = tid >> 6;
        float4 g4 = *(const float4*)&lng[cl];
        float4 b4 = *(const float4*)&lnb[cl];
        int h = cl >> 6, cc = cl & 63;
        const float qscale = 0.125f * LOG2E_;
        long long obase = ((long long)(b * NH_ + h) * DZ_ + z) * HW_;
        for (int r = rb; r < 64; r += 4) {
            float mu = smean[r], rs = srstd[r];
            float v0 = ((s_o[r * 260 + cl] - mu) * rs * g4.x + b4.x) * qscale;
            float v1 = ((s_o[r * 260 + cl + 1] - mu) * rs * g4.y + b4.y) * qscale;
            float v2 = ((s_o[r * 260 + cl + 2] - mu) * rs * g4.z + b4.z) * qscale;
            float v3 = ((s_o[r * 260 + cl + 3] - mu) * rs * g4.w + b4.w) * qscale;
            uint2 u = make_uint2(pk2(v0, v1), pk2(v2, v3));
            *(uint2*)&g_Q[(obase + p0 + r) * HD_ + cc] = u;
        }
    }
}

__device__ void kvproj_body(int job, const float* __restrict__ F2,
                            const float* __restrict__ lng,
                            const float* __restrict__ lnb, float* ksm) {
    float* xk = ksm;                  // [96][72]
    float* bs = ksm + 96 * 72;        // [256][33]
    float* s_o = ksm;                 // alias at base (xk/bs dead post-mma)
    __shared__ float smean[64], srstd[64];

    int mat = job & 1;
    int sp = job >> 1;
    int p0 = (sp % 9) * 64;
    int k = (sp / 9) % K_;
    int b = sp / (9 * K_);

    int tid = threadIdx.x;
    int w = tid >> 5, lane = tid & 31;
    int g = lane >> 2, t = lane & 3;
    int mt = w & 3, nh = w >> 2;

    {
        int r = tid & 63;
        int cb = tid >> 6;
        for (int c = cb; c < C2_; c += 4)
            xk[c * 72 + r] = F2[((b * C2_ + c) * HW_ + p0 + r) * K_ + k];
    }

    const float* WT = mat == 0 ? g_WkT : g_WvT;
    float4 acc[16];
#pragma unroll
    for (int n = 0; n < 16; n++) acc[n] = make_float4(0.f, 0.f, 0.f, 0.f);

    for (int kb = 0; kb < 3; kb++) {
        __syncthreads();
        {
            int kk = tid & 31;
            int n0 = tid >> 5;
            for (int n = n0; n < 256; n += 8)
                bs[n * 33 + kk] = WT[n * C2_ + kb * 32 + kk];
        }
        __syncthreads();
#pragma unroll
        for (int kcl = 0; kcl < 4; kcl++) {
            int krow = kb * 32 + kcl * 8;
            int arow = mt * 16 + g;
            unsigned a0 = __float_as_uint(xk[(krow + t) * 72 + arow]);
            unsigned a1 = __float_as_uint(xk[(krow + t) * 72 + arow + 8]);
            unsigned a2 = __float_as_uint(xk[(krow + t + 4) * 72 + arow]);
            unsigned a3 = __float_as_uint(xk[(krow + t + 4) * 72 + arow + 8]);
#pragma unroll
            for (int n = 0; n < 16; n++) {
                const float* br = &bs[(nh * 128 + n * 8 + g) * 33 + kcl * 8];
                mma_tf32(acc[n], a0, a1, a2, a3,
                         __float_as_uint(br[t]), __float_as_uint(br[t + 4]));
            }
        }
    }
    __syncthreads();
    {
        int rl = mt * 16 + g;
#pragma unroll
        for (int n = 0; n < 16; n++) {
            int col = nh * 128 + n * 8 + 2 * t;
            s_o[rl * 260 + col] = acc[n].x;
            s_o[rl * 260 + col + 1] = acc[n].y;
            s_o[(rl + 8) * 260 + col] = acc[n].z;
            s_o[(rl + 8) * 260 + col + 1] = acc[n].w;
        }
    }
    __syncthreads();
#pragma unroll
    for (int rr = 0; rr < 8; rr++) {
        int row = w * 8 + rr;
        float s = 0.f, q = 0.f;
#pragma unroll
        for (int jj = 0; jj < 8; jj++) {
            float v = s_o[row * 260 + lane + 32 * jj];
            s += v; q += v * v;
        }
#pragma unroll
        for (int off = 16; off >= 1; off >>= 1) {
            s += __shfl_xor_sync(0xffffffffu, s, off);
            q += __shfl_xor_sync(0xffffffffu, q, off);
        }
        if (lane == 0) {
            float mu = s * (1.f / 256.f);
            smean[row] = mu;
            srstd[row] = rsqrtf(q * (1.f / 256.f) - mu * mu + LN_EPS);
        }
    }
    __syncthreads();

    if (mat == 0) {
        int cl = (tid & 63) * 4;
        int rb = tid >> 6;
        float4 g4 = *(const float4*)&lng[cl];
        float4 b4 = *(const float4*)&lnb[cl];
        int h = cl >> 6, cc = cl & 63;
        long long obase = ((long long)(b * NH_ + h) * K_ + k) * HW_;
        for (int r = rb; r < 64; r += 4) {
            float mu = smean[r], rs = srstd[r];
            float v0 = (s_o[r * 260 + cl] - mu) * rs * g4.x + b4.x;
            float v1 = (s_o[r * 260 + cl + 1] - mu) * rs * g4.y + b4.y;
            float v2 = (s_o[r * 260 + cl + 2] - mu) * rs * g4.z + b4.z;
            float v3 = (s_o[r * 260 + cl + 3] - mu) * rs * g4.w + b4.w;
            uint2 u = make_uint2(pk2(v0, v1), pk2(v2, v3));
            *(uint2*)&g_K[(obase + p0 + r) * HD_ + cc] = u;
        }
    } else {
        int e = tid;
        float ge = lng[e], be = lnb[e];
        int h = e >> 6, d = e & 63;
        long long vb = (((long long)(b * NH_ + h) * K_ + k) * HD_ + d) * HW_ + p0;
#pragma unroll
        for (int rb2 = 0; rb2 < 16; rb2++) {
            int r = rb2 * 4;
            float v0 = (s_o[r * 260 + e] - smean[r]) * srstd[r] * ge + be;
            float v1 = (s_o[(r + 1) * 260 + e] - smean[r + 1]) * srstd[r + 1] * ge + be;
            float v2 = (s_o[(r + 2) * 260 + e] - smean[r + 2]) * srstd[r + 2] * ge + be;
            float v3 = (s_o[(r + 3) * 260 + e] - smean[r + 3]) * srstd[r + 3] * ge + be;
            uint2 u = make_uint2(pkh(v0, v1), pkh(v2, v3));   // fp16 V
            *(uint2*)&g_Vt[vb + r] = u;
        }
    }
}

#define NJ_CONV 96
#define NJ_Q 576
#define NJ_KV 288
__global__ __launch_bounds__(256) void k_front(const float* __restrict__ F2,
                                               const float* __restrict__ F3,
                                               const float* __restrict__ bng,
                                               const float* __restrict__ bnb,
                                               const float* __restrict__ lnkg,
                                               const float* __restrict__ lnkb,
                                               const float* __restrict__ lnqg,
                                               const float* __restrict__ lnqb) {
    extern __shared__ float fsm[];
    int job = blockIdx.x;
    if (job < NJ_CONV) {
        conv1_body(job, F2, bng, bnb, fsm);
    } else if (job < NJ_CONV + NJ_Q) {
        qproj_body(job - NJ_CONV, F3, lnqg, lnqb, fsm);
    } else {
        kvproj_body(job - NJ_CONV - NJ_Q, F2, lnkg, lnkb, fsm);
    }
}

// ------------------- kernel 2: conv2 1x1 + neighbor-sum -> topo -------------
__global__ __launch_bounds__(192) void k_topo(const float* __restrict__ w2,
                                              const float* __restrict__ w2b) {
    __shared__ float sp[HW_];
    __shared__ float wsh[64];
    int bk = blockIdx.x;
    int tid = threadIdx.x;
    if (tid < 64) wsh[tid] = w2[tid];
    __syncthreads();
    for (int p = tid; p < HW_; p += 192) {
        const float* hp = &g_h[(bk * HW_ + p) * TOPO_];
        float s = w2b[0];
#pragma unroll
        for (int o = 0; o < 64; o += 4) {
            float4 hv = *(const float4*)&hp[o];
            s += hv.x * wsh[o] + hv.y * wsh[o + 1] + hv.z * wsh[o + 2] + hv.w * wsh[o + 3];
        }
        sp[p] = s;
    }
    __syncthreads();
    for (int p = tid; p < HW_; p += 192) {
        int y = p / 24, x = p % 24;
        float s = 0.f;
#pragma unroll
        for (int dy = -1; dy <= 1; dy++)
#pragma unroll
            for (int dx = -1; dx <= 1; dx++) {
                if (dy == 0 && dx == 0) continue;
                int yy = y + dy, xx = x + dx;
                if ((unsigned)yy < 24u && (unsigned)xx < 24u) s += sp[yy * 24 + xx];
            }
        g_topo[bk * HW_ + p] = sp[p] + 0.5f * s;
    }
}

// ------ kernel 5: flash attention (96-key tiles, hoisted Q, per-chunk) ------
#define BST 72
#define VST 104
__global__ __launch_bounds__(128) void k_attn(const float* __restrict__ lam_p,
                                              const void* __restrict__ D0_p,
                                              const void* __restrict__ slab_p) {
    extern __shared__ __nv_bfloat16 bsm[];
    __nv_bfloat16* Qs = bsm;                       // [128][72]
    __nv_bfloat16* Ks = bsm + 128 * BST;           // [96][72]  (key, dim)
    __half* Vs = (__half*)(bsm + 224 * BST);       // [64][104] (dim, key) fp16

    int bid = blockIdx.x;
    int p0 = (bid % 9) * 64;
    int zp = (bid / 9) % (DZ_ / 2);
    int h = (bid / (9 * (DZ_ / 2))) % NH_;
    int b = bid / (9 * (DZ_ / 2) * NH_);
    int z0 = zp * 2;

    int D0 = flex_int(D0_p, 128);
    int slab = flex_int(slab_p, 16);
    float lam2 = (*lam_p) * LOG2E_;

    int kkz[2], cloz[2], chiz[2];
#pragma unroll
    for (int i = 0; i < 2; i++) {
        int zz = z0 + i;
        int zq = (int)llrint((double)(D0 - 1) * (double)zz / (double)(DZ_ - 1));
        int kk = zq / slab;
        if (kk < 0) kk = 0;
        if (kk > K_ - 1) kk = K_ - 1;
        kkz[i] = kk;
        cloz[i] = (kk - 1 < 0) ? 0 : kk - 1;
        chiz[i] = (kk + 1 > K_ - 1) ? K_ - 1 : kk + 1;
    }
    int cU_lo = min(cloz[0], cloz[1]);
    int cU_hi = max(chiz[0], chiz[1]);

    int tid = threadIdx.x;
    int w = tid >> 5;
    int lane = tid & 31;
    int g = lane >> 2;
    int t = lane & 3;

    int wz = w >> 1;
    int zw = z0 + wz;
    int kk_w = kkz[wz], clo_w = cloz[wz], chi_w = chiz[wz];
    int prow = p0 + (w & 1) * 32;
    int qrow = w * 32;

    unsigned qb_s = (unsigned)__cvta_generic_to_shared(Qs);
    unsigned kb_s = (unsigned)__cvta_generic_to_shared(Ks);
    unsigned vb_s = (unsigned)__cvta_generic_to_shared(Vs);
    int lrow = (lane & 7) + ((lane >> 3) & 1) * 8;
    int lcol = ((lane >> 4) & 1) * 8;
    unsigned laneoff  = (lrow * BST + lcol) * 2;
    unsigned laneoffV = (lrow * VST + lcol) * 2;

    {
        long long qb0 = ((((long long)(b * NH_ + h) * DZ_ + z0) * HW_) + p0) * HD_;
#pragma unroll
        for (int it = 0; it < 8; it++) {
            int idx = tid + it * 128;
            int r = idx >> 3, v = (idx & 7) * 8;
            long long src = qb0 + (long long)(r >> 6) * (HW_ * HD_) + (long long)(r & 63) * 64 + v;
            *(uint4*)&Qs[r * BST + v] = *(const uint4*)&g_Q[src];
        }
    }
    __syncthreads();

    // hoisted Q fragments (tile-invariant)
    unsigned qf0[4][4], qf1[4][4];
#pragma unroll
    for (int kc = 0; kc < 4; kc++) {
        int kc16 = kc * 16;
        ldsm4(qf0[kc][0], qf0[kc][1], qf0[kc][2], qf0[kc][3],
              qb_s + (qrow * BST + kc16) * 2 + laneoff);
        ldsm4(qf1[kc][0], qf1[kc][1], qf1[kc][2], qf1[kc][3],
              qb_s + ((qrow + 16) * BST + kc16) * 2 + laneoff);
    }

    float4 lacc0 = make_float4(0.f, 0.f, 0.f, 0.f);
    float4 lacc1 = make_float4(0.f, 0.f, 0.f, 0.f);
    float4 O0[8], O1[8];
#pragma unroll
    for (int n = 0; n < 8; n++) {
        O0[n] = make_float4(0.f, 0.f, 0.f, 0.f);
        O1[n] = make_float4(0.f, 0.f, 0.f, 0.f);
    }

    for (int c = cU_lo; c <= cU_hi; c++) {
        bool active = (c >= clo_w) && (c <= chi_w);
        float bias2 = (c == kk_w) ? 0.f : -0.5f * LOG2E_;
        long long kb = (((long long)(b * NH_ + h) * K_ + c) * HW_) * HD_;
        long long vb = (((long long)(b * NH_ + h) * K_ + c) * HD_) * HW_;
        const float* topo_c = &g_topo[(b * K_ + c) * HW_];
        for (int pk0 = 0; pk0 < HW_; pk0 += 96) {
            __syncthreads();
#pragma unroll
            for (int it = 0; it < 6; it++) {
                int idx = tid + it * 128;                 // 0..767
                int rK = idx >> 3, vK = (idx & 7) * 8;    // 96 rows x 8 uint4
                *(uint4*)&Ks[rK * BST + vK] = *(const uint4*)&g_K[kb + (long long)(pk0 + rK) * 64 + vK];
                int rV = idx / 12, vV = (idx % 12) * 8;   // 64 rows x 12 uint4
                *(uint4*)&Vs[rV * VST + vV] = *(const uint4*)&g_Vt[vb + (long long)rV * HW_ + pk0 + vV];
            }
            __syncthreads();
            if (!active) continue;

            bool diag = (pk0 < p0 + 64) && (pk0 + 96 > p0);
            int rq0 = prow + g;
            int rq1 = prow + 16 + g;

#pragma unroll
            for (int n2 = 0; n2 < 6; n2++) {
                int kc16 = n2 * 16;
                // ---- S for key chunk n2 (16 keys), both stripes ----
                float4 S0a = make_float4(0.f, 0.f, 0.f, 0.f);
                float4 S0b = make_float4(0.f, 0.f, 0.f, 0.f);
                float4 S1a = make_float4(0.f, 0.f, 0.f, 0.f);
                float4 S1b = make_float4(0.f, 0.f, 0.f, 0.f);
#pragma unroll
                for (int kc = 0; kc < 4; kc++) {
                    unsigned b0, b1, b2, b3;
                    ldsm4(b0, b1, b2, b3, kb_s + (kc16 * BST + kc * 16) * 2 + laneoff);
                    mma_bf16(S0a, qf0[kc][0], qf0[kc][1], qf0[kc][2], qf0[kc][3], b0, b2);
                    mma_bf16(S0b, qf0[kc][0], qf0[kc][1], qf0[kc][2], qf0[kc][3], b1, b3);
                    mma_bf16(S1a, qf1[kc][0], qf1[kc][1], qf1[kc][2], qf1[kc][3], b0, b2);
                    mma_bf16(S1b, qf1[kc][0], qf1[kc][1], qf1[kc][2], qf1[kc][3], b1, b3);
                }

                // ---- bias (+ diagonal topo only in overlapping tiles) ----
                if (diag) {
                    int j0a = pk0 + n2 * 16 + 2 * t;
                    int j0b = j0a + 8;
                    float da0 = bias2, da1 = bias2, da2 = bias2, da3 = bias2;
                    float db0 = bias2, db1 = bias2, db2 = bias2, db3 = bias2;
                    float ea0 = bias2, ea1 = bias2, ea2 = bias2, ea3 = bias2;
                    float eb0 = bias2, eb1 = bias2, eb2 = bias2, eb3 = bias2;
                    if (rq0 == j0a)         da0 += lam2 * topo_c[j0a];
                    if (rq0 == j0a + 1)     da1 += lam2 * topo_c[j0a + 1];
                    if (rq0 + 8 == j0a)     da2 += lam2 * topo_c[j0a];
                    if (rq0 + 8 == j0a + 1) da3 += lam2 * topo_c[j0a + 1];
                    if (rq0 == j0b)         db0 += lam2 * topo_c[j0b];
                    if (rq0 == j0b + 1)     db1 += lam2 * topo_c[j0b + 1];
                    if (rq0 + 8 == j0b)     db2 += lam2 * topo_c[j0b];
                    if (rq0 + 8 == j0b + 1) db3 += lam2 * topo_c[j0b + 1];
                    if (rq1 == j0a)         ea0 += lam2 * topo_c[j0a];
                    if (rq1 == j0a + 1)     ea1 += lam2 * topo_c[j0a + 1];
                    if (rq1 + 8 == j0a)     ea2 += lam2 * topo_c[j0a];
                    if (rq1 + 8 == j0a + 1) ea3 += lam2 * topo_c[j0a + 1];
                    if (rq1 == j0b)         eb0 += lam2 * topo_c[j0b];
                    if (rq1 == j0b + 1)     eb1 += lam2 * topo_c[j0b + 1];
                    if (rq1 + 8 == j0b)     eb2 += lam2 * topo_c[j0b];
                    if (rq1 + 8 == j0b + 1) eb3 += lam2 * topo_c[j0b + 1];
                    S0a.x += da0; S0a.y += da1; S0a.z += da2; S0a.w += da3;
                    S0b.x += db0; S0b.y += db1; S0b.z += db2; S0b.w += db3;
                    S1a.x += ea0; S1a.y += ea1; S1a.z += ea2; S1a.w += ea3;
                    S1b.x += eb0; S1b.y += eb1; S1b.z += eb2; S1b.w += eb3;
                } else {
                    S0a.x += bias2; S0a.y += bias2; S0a.z += bias2; S0a.w += bias2;
                    S0b.x += bias2; S0b.y += bias2; S0b.z += bias2; S0b.w += bias2;
                    S1a.x += bias2; S1a.y += bias2; S1a.z += bias2; S1a.w += bias2;
                    S1b.x += bias2; S1b.y += bias2; S1b.z += bias2; S1b.w += bias2;
                }

                // ---- P = exp2(S) packed fp16; l via ones-mma; O += P*V ----
                unsigned a00 = ex2h(pkh(S0a.x, S0a.y));
                unsigned a01 = ex2h(pkh(S0a.z, S0a.w));
                unsigned a02 = ex2h(pkh(S0b.x, S0b.y));
                unsigned a03 = ex2h(pkh(S0b.z, S0b.w));
                unsigned a10 = ex2h(pkh(S1a.x, S1a.y));
                unsigned a11 = ex2h(pkh(S1a.z, S1a.w));
                unsigned a12 = ex2h(pkh(S1b.x, S1b.y));
                unsigned a13 = ex2h(pkh(S1b.z, S1b.w));
                mma_f16(lacc0, a00, a01, a02, a03, ONESH, ONESH);
                mma_f16(lacc1, a10, a11, a12, a13, ONESH, ONESH);
#pragma unroll
                for (int n2v = 0; n2v < 4; n2v++) {
                    unsigned b0, b1, b2, b3;
                    ldsm4(b0, b1, b2, b3, vb_s + ((n2v * 16) * VST + kc16) * 2 + laneoffV);
                    mma_f16(O0[2 * n2v],     a00, a01, a02, a03, b0, b2);
                    mma_f16(O0[2 * n2v + 1], a00, a01, a02, a03, b1, b3);
                    mma_f16(O1[2 * n2v],     a10, a11, a12, a13, b0, b2);
                    mma_f16(O1[2 * n2v + 1], a10, a11, a12, a13, b1, b3);
                }
            }
        }
    }

    float i00 = 1.f / lacc0.x, i01 = 1.f / lacc0.z;
    float i10 = 1.f / lacc1.x, i11 = 1.f / lacc1.z;
    long long ob = ((long long)(b * DZ_ + zw) * HW_) * E_ + h * HD_;
    int rq0 = prow + g, rq1 = prow + 16 + g;
#pragma unroll
    for (int n = 0; n < 8; n++) {
        int col = n * 8 + 2 * t;
        *(float2*)&g_O[ob + (long long)rq0 * E_ + col] = make_float2(O0[n].x * i00, O0[n].y * i00);
        *(float2*)&g_O[ob + (long long)(rq0 + 8) * E_ + col] = make_float2(O0[n].z * i01, O0[n].w * i01);
        *(float2*)&g_O[ob + (long long)rq1 * E_ + col] = make_float2(O1[n].x * i10, O1[n].y * i10);
        *(float2*)&g_O[ob + (long long)(rq1 + 8) * E_ + col] = make_float2(O1[n].z * i11, O1[n].w * i11);
    }
}

// ------------------- kernel 6: output projection + residual (tf32 MMA) ------
__global__ __launch_bounds__(256) void k_oproj(const float* __restrict__ F3,
                                               float* __restrict__ out) {
    extern __shared__ float osm[];
    float* bs = osm;                  // [128][33]
    float* s_o = osm + 128 * 33;      // [128 cols][68 rows]
    int bid = blockIdx.x;
    int p0 = (bid % 9) * 64;
    int z = (bid / 9) % DZ_;
    int b = bid / (9 * DZ_);

    int tid = threadIdx.x;
    int w = tid >> 5, lane = tid & 31;
    int g = lane >> 2, t = lane & 3;
    int mt = w & 3, nh = w >> 2;

    int rowl = (b * DZ_ + z) * HW_ + p0 + mt * 16 + g;
    const float* Al = &g_O[(long long)rowl * E_];
    const float* Ah = Al + 8LL * E_;

    float4 acc[8];
#pragma unroll
    for (int n = 0; n < 8; n++) acc[n] = make_float4(0.f, 0.f, 0.f, 0.f);

    for (int kb = 0; kb < 8; kb++) {
        __syncthreads();
        {
            int kk = tid & 31;
            int n0 = tid >> 5;
            for (int n = n0; n < 128; n += 8)
                bs[n * 33 + kk] = g_WpT[n * E_ + kb * 32 + kk];
        }
        __syncthreads();
#pragma unroll
        for (int kcl = 0; kcl < 4; kcl++) {
            int kcol = kb * 32 + kcl * 8;
            unsigned a0 = __float_as_uint(Al[kcol + t]);
            unsigned a1 = __float_as_uint(Ah[kcol + t]);
            unsigned a2 = __float_as_uint(Al[kcol + t + 4]);
            unsigned a3 = __float_as_uint(Ah[kcol + t + 4]);
#pragma unroll
            for (int n = 0; n < 8; n++) {
                const float* br = &bs[(nh * 64 + n * 8 + g) * 33 + kcl * 8];
                mma_tf32(acc[n], a0, a1, a2, a3,
                         __float_as_uint(br[t]), __float_as_uint(br[t + 4]));
            }
        }
    }
    __syncthreads();

    {
        int rl = mt * 16 + g;
#pragma unroll
        for (int n = 0; n < 8; n++) {
            int col = nh * 64 + n * 8 + 2 * t;
            s_o[col * 68 + rl] = acc[n].x;
            s_o[(col + 1) * 68 + rl] = acc[n].y;
            s_o[col * 68 + rl + 8] = acc[n].z;
            s_o[(col + 1) * 68 + rl + 8] = acc[n].w;
        }
    }
    __syncthreads();

    {
        int r = tid & 63;
        int cb = tid >> 6;
        for (int c = cb; c < C3_; c += 4) {
            long long oi = (long long)(b * C3_ + c) * (DZ_ * HW_) + z * HW_ + p0 + r;
            out[oi] = F3[oi] + s_o[c * 68 + r];
        }
    }
}

// ----------------------------------- launch ---------------------------------
extern "C" void kernel_launch(void* const* d_in, const int* in_sizes, int n_in,
                              void* d_out, int out_size) {
    const float* F3  = (const float*)d_in[0];
    const float* F2  = (const float*)d_in[1];
    const float* Wq  = (const float*)d_in[2];
    const float* Wk  = (const float*)d_in[3];
    const float* Wv  = (const float*)d_in[4];
    const float* Wp  = (const float*)d_in[5];
    const float* lnqg = (const float*)d_in[6];
    const float* lnqb = (const float*)d_in[7];
    const float* lnkg = (const float*)d_in[8];
    const float* lnkb = (const float*)d_in[9];
    const float* w1   = (const float*)d_in[10];
    const float* bng  = (const float*)d_in[11];
    const float* bnb  = (const float*)d_in[12];
    const float* w2   = (const float*)d_in[13];
    const float* w2b  = (const float*)d_in[14];
    const float* lam  = (const float*)d_in[15];
    const void*  D0p  = d_in[16];
    const void*  slabp = d_in[17];
    float* out = (float*)d_out;

    int front_smem = (128 * 72 + 256 * 33) * (int)sizeof(float);    // 70656 (qproj max)
    int attn_smem  = (224 * BST + 64 * VST) * 2;                    // 45568
    int oproj_smem = (128 * 33 + 128 * 68) * (int)sizeof(float);    // 51712
    static int cfg_done = 0;
    if (!cfg_done) {
        cudaFuncSetAttribute(k_front, cudaFuncAttributeMaxDynamicSharedMemorySize, front_smem);
        cudaFuncSetAttribute(k_attn, cudaFuncAttributeMaxDynamicSharedMemorySize, attn_smem);
        cudaFuncSetAttribute(k_oproj, cudaFuncAttributeMaxDynamicSharedMemorySize, oproj_smem);
        cfg_done = 1;
    }

    k_wprep<<<(TOPO_ * C2_ * 9 + 255) / 256, 256>>>(w1, Wq, Wp, Wk, Wv);
    k_front<<<NJ_CONV + NJ_Q + NJ_KV, 256, front_smem>>>(F2, F3, bng, bnb,
                                                         lnkg, lnkb, lnqg, lnqb);
    k_topo<<<B_ * K_, 192>>>(w2, w2b);
    k_attn<<<B_ * NH_ * (DZ_ / 2) * 9, 128, attn_smem>>>(lam, D0p, slabp);
    k_oproj<<<B_ * DZ_ * 9, 256, oproj_smem>>>(F3, out);
}

// round 15
// speedup vs baseline: 1.5501x; 1.5501x over previous
#include <cuda_runtime.h>
#include <cuda_bf16.h>
#include <cuda_fp16.h>
#include <math.h>

#define B_ 2
#define C3_ 128
#define DZ_ 32
#define HW_ 576
#define C2_ 96
#define K_ 8
#define E_ 256
#define NH_ 4
#define HD_ 64
#define TOPO_ 64
#define LN_EPS 1e-5f
#define LOG2E_ 1.4426950408889634f
#define ONESH 0x3C003C00u   // fp16 {1.0, 1.0}

// ------------------------- device scratch (no allocation) -------------------
__device__ float g_w1t[C2_ * 9 * TOPO_];
__device__ float g_h[B_ * K_ * HW_ * TOPO_];
__device__ float g_topo[B_ * K_ * HW_];
__device__ __nv_bfloat16 g_Q[B_ * NH_ * DZ_ * HW_ * HD_];   // pre-scaled by log2e/8
__device__ __nv_bfloat16 g_K[B_ * NH_ * K_ * HW_ * HD_];    // (b,h,c,p,d)
__device__ __half g_Vt[B_ * NH_ * K_ * HD_ * HW_];          // (b,h,c,d,p) fp16, transposed
__device__ float g_O[B_ * DZ_ * HW_ * E_];
__device__ float g_WqT[E_ * C3_];
__device__ float g_WpT[C3_ * E_];
__device__ float g_WkT[E_ * C2_];
__device__ float g_WvT[E_ * C2_];

__device__ __forceinline__ int flex_int(const void* p, int dflt) {
    int v = *(const int*)p;
    if (v >= 1 && v <= 1000000) return v;
    float f = *(const float*)p;
    if (f >= 1.f && f <= 1000000.f) return (int)f;
    return dflt;
}

__device__ __forceinline__ unsigned pk2(float lo, float hi) {          // bf16x2
    unsigned r;
    asm("cvt.rn.bf16x2.f32 %0, %1, %2;" : "=r"(r) : "f"(hi), "f"(lo));
    return r;
}

__device__ __forceinline__ unsigned pkh(float lo, float hi) {          // f16x2
    unsigned r;
    asm("cvt.rn.f16x2.f32 %0, %1, %2;" : "=r"(r) : "f"(hi), "f"(lo));
    return r;
}

__device__ __forceinline__ unsigned ex2h(unsigned x) {                 // exp2 on f16x2
    unsigned y;
    asm("ex2.approx.f16x2 %0, %1;" : "=r"(y) : "r"(x));
    return y;
}

__device__ __forceinline__ void ldsm4(unsigned& r0, unsigned& r1,
                                      unsigned& r2, unsigned& r3, unsigned addr) {
    asm volatile("ldmatrix.sync.aligned.m8n8.x4.shared.b16 {%0,%1,%2,%3}, [%4];"
                 : "=r"(r0), "=r"(r1), "=r"(r2), "=r"(r3) : "r"(addr));
}

__device__ __forceinline__ void mma_tf32(float4& d,
                                         unsigned a0, unsigned a1, unsigned a2, unsigned a3,
                                         unsigned b0, unsigned b1) {
    asm volatile(
        "mma.sync.aligned.m16n8k8.row.col.f32.tf32.tf32.f32 "
        "{%0,%1,%2,%3}, {%4,%5,%6,%7}, {%8,%9}, {%0,%1,%2,%3};"
        : "+f"(d.x), "+f"(d.y), "+f"(d.z), "+f"(d.w)
        : "r"(a0), "r"(a1), "r"(a2), "r"(a3), "r"(b0), "r"(b1));
}

__device__ __forceinline__ void mma_bf16(float4& d,
                                         unsigned a0, unsigned a1, unsigned a2, unsigned a3,
                                         unsigned b0, unsigned b1) {
    asm volatile(
        "mma.sync.aligned.m16n8k16.row.col.f32.bf16.bf16.f32 "
        "{%0,%1,%2,%3}, {%4,%5,%6,%7}, {%8,%9}, {%0,%1,%2,%3};"
        : "+f"(d.x), "+f"(d.y), "+f"(d.z), "+f"(d.w)
        : "r"(a0), "r"(a1), "r"(a2), "r"(a3), "r"(b0), "r"(b1));
}

__device__ __forceinline__ void mma_f16(float4& d,
                                        unsigned a0, unsigned a1, unsigned a2, unsigned a3,
                                        unsigned b0, unsigned b1) {
    asm volatile(
        "mma.sync.aligned.m16n8k16.row.col.f32.f16.f16.f32 "
        "{%0,%1,%2,%3}, {%4,%5,%6,%7}, {%8,%9}, {%0,%1,%2,%3};"
        : "+f"(d.x), "+f"(d.y), "+f"(d.z), "+f"(d.w)
        : "r"(a0), "r"(a1), "r"(a2), "r"(a3), "r"(b0), "r"(b1));
}

// ------------------------- kernel 0: all weight prep ------------------------
__global__ void k_wprep(const float* __restrict__ w1,
                        const float* __restrict__ Wq, const float* __restrict__ Wp,
                        const float* __restrict__ Wk, const float* __restrict__ Wv) {
    int i = blockIdx.x * 256 + threadIdx.x;
    if (i < TOPO_ * C2_ * 9) {
        int o = i / (C2_ * 9);
        int r = i % (C2_ * 9);
        int c = r / 9, tap = r % 9;
        g_w1t[(c * 9 + tap) * TOPO_ + o] = w1[i];
    }
    if (i < C3_ * E_) {
        int e = i / C3_, c = i % C3_;
        g_WqT[i] = Wq[c * E_ + e];
        g_WpT[c * E_ + e] = Wp[i];
    }
    if (i < C2_ * E_) {
        int e = i / C2_, c = i % C2_;
        g_WkT[i] = Wk[c * E_ + e];
        g_WvT[i] = Wv[c * E_ + e];
    }
}

// ===================== fused front: conv1 | qproj | kvproj ==================
__device__ void conv1_body(int job, const float* __restrict__ F2,
                           const float* __restrict__ bng,
                           const float* __restrict__ bnb, float* sm) {
    float* in_s = sm;            // [16][6][26]
    float* w_s = sm + 2496;      // [16*9*64]
    int bk = job / 6;
    int y0 = (job % 6) * 4;
    int b = bk >> 3, k = bk & 7;
    int tid = threadIdx.x;
    int pg = tid >> 3;
    int og = tid & 7;
    int pl = pg * 3;
    int yrel = pl / 24;
    int x0 = pl % 24;
    int o0 = og * 8;
    float acc[3][8];
#pragma unroll
    for (int u = 0; u < 3; u++)
#pragma unroll
        for (int v = 0; v < 8; v++) acc[u][v] = 0.f;

    for (int c0 = 0; c0 < C2_; c0 += 16) {
        __syncthreads();
        for (int idx = tid; idx < 16 * 6 * 26; idx += 256) {
            int cc = idx / 156, rem = idx % 156;
            int yy = rem / 26, xx = rem % 26;
            int y = y0 - 1 + yy, x = xx - 1;
            float v = 0.f;
            if ((unsigned)y < 24u && (unsigned)x < 24u)
                v = F2[((b * C2_ + c0 + cc) * HW_ + y * 24 + x) * K_ + k];
            in_s[cc * 156 + yy * 26 + xx] = v;
        }
        for (int idx = tid; idx < 16 * 9 * 64; idx += 256)
            w_s[idx] = g_w1t[c0 * 9 * 64 + idx];
        __syncthreads();
        for (int cc = 0; cc < 16; cc++) {
#pragma unroll
            for (int dy = 0; dy < 3; dy++) {
                float rv[5];
#pragma unroll
                for (int u = 0; u < 5; u++) rv[u] = in_s[cc * 156 + (yrel + dy) * 26 + x0 + u];
#pragma unroll
                for (int dx = 0; dx < 3; dx++) {
                    const float* wp = &w_s[(cc * 9 + dy * 3 + dx) * 64 + o0];
                    float4 wa = *(const float4*)wp;
                    float4 wb = *(const float4*)(wp + 4);
#pragma unroll
                    for (int u = 0; u < 3; u++) {
                        float a = rv[u + dx];
                        acc[u][0] += a * wa.x; acc[u][1] += a * wa.y;
                        acc[u][2] += a * wa.z; acc[u][3] += a * wa.w;
                        acc[u][4] += a * wb.x; acc[u][5] += a * wb.y;
                        acc[u][6] += a * wb.z; acc[u][7] += a * wb.w;
                    }
                }
            }
        }
    }
    float invs = rsqrtf(1.f + LN_EPS);
    float sg[8], sb[8];
#pragma unroll
    for (int v = 0; v < 8; v++) { sg[v] = bng[o0 + v] * invs; sb[v] = bnb[o0 + v]; }
#pragma unroll
    for (int u = 0; u < 3; u++) {
        int p = (y0 + yrel) * 24 + x0 + u;
        float4 h0, h1;
        h0.x = fmaxf(acc[u][0] * sg[0] + sb[0], 0.f);
        h0.y = fmaxf(acc[u][1] * sg[1] + sb[1], 0.f);
        h0.z = fmaxf(acc[u][2] * sg[2] + sb[2], 0.f);
        h0.w = fmaxf(acc[u][3] * sg[3] + sb[3], 0.f);
        h1.x = fmaxf(acc[u][4] * sg[4] + sb[4], 0.f);
        h1.y = fmaxf(acc[u][5] * sg[5] + sb[5], 0.f);
        h1.z = fmaxf(acc[u][6] * sg[6] + sb[6], 0.f);
        h1.w = fmaxf(acc[u][7] * sg[7] + sb[7], 0.f);
        *(float4*)&g_h[(bk * HW_ + p) * TOPO_ + o0] = h0;
        *(float4*)&g_h[(bk * HW_ + p) * TOPO_ + o0 + 4] = h1;
    }
}

__device__ void qproj_body(int job, const float* __restrict__ F3,
                           const float* __restrict__ lng,
                           const float* __restrict__ lnb, float* qsm) {
    float* xk = qsm;                  // [128][72]
    float* bs = qsm + 128 * 72;       // [256][33]
    float* s_o = qsm;                 // alias, [64][260]
    __shared__ float smean[64], srstd[64];

    int p0 = (job % 9) * 64;
    int z = (job / 9) % DZ_;
    int b = job / (9 * DZ_);

    int tid = threadIdx.x;
    int w = tid >> 5, lane = tid & 31;
    int g = lane >> 2, t = lane & 3;
    int mt = w & 3, nh = w >> 2;

    {
        int r = tid & 63;
        int cb = tid >> 6;
        for (int c = cb; c < C3_; c += 4)
            xk[c * 72 + r] = F3[(b * C3_ + c) * (DZ_ * HW_) + z * HW_ + p0 + r];
    }

    float4 acc[16];
#pragma unroll
    for (int n = 0; n < 16; n++) acc[n] = make_float4(0.f, 0.f, 0.f, 0.f);

    for (int kb = 0; kb < 4; kb++) {
        __syncthreads();
        {
            int kk = tid & 31;
            int n0 = tid >> 5;
            for (int n = n0; n < 256; n += 8)
                bs[n * 33 + kk] = g_WqT[n * C3_ + kb * 32 + kk];
        }
        __syncthreads();
#pragma unroll
        for (int kcl = 0; kcl < 4; kcl++) {
            int krow = kb * 32 + kcl * 8;
            int arow = mt * 16 + g;
            unsigned a0 = __float_as_uint(xk[(krow + t) * 72 + arow]);
            unsigned a1 = __float_as_uint(xk[(krow + t) * 72 + arow + 8]);
            unsigned a2 = __float_as_uint(xk[(krow + t + 4) * 72 + arow]);
            unsigned a3 = __float_as_uint(xk[(krow + t + 4) * 72 + arow + 8]);
#pragma unroll
            for (int n = 0; n < 16; n++) {
                const float* br = &bs[(nh * 128 + n * 8 + g) * 33 + kcl * 8];
                mma_tf32(acc[n], a0, a1, a2, a3,
                         __float_as_uint(br[t]), __float_as_uint(br[t + 4]));
            }
        }
    }
    __syncthreads();

    {
        int rl = mt * 16 + g;
#pragma unroll
        for (int n = 0; n < 16; n++) {
            int col = nh * 128 + n * 8 + 2 * t;
            s_o[rl * 260 + col] = acc[n].x;
            s_o[rl * 260 + col + 1] = acc[n].y;
            s_o[(rl + 8) * 260 + col] = acc[n].z;
            s_o[(rl + 8) * 260 + col + 1] = acc[n].w;
        }
    }
    __syncthreads();

#pragma unroll
    for (int rr = 0; rr < 8; rr++) {
        int row = w * 8 + rr;
        float s = 0.f, q = 0.f;
#pragma unroll
        for (int jj = 0; jj < 8; jj++) {
            float v = s_o[row * 260 + lane + 32 * jj];
            s += v; q += v * v;
        }
#pragma unroll
        for (int off = 16; off >= 1; off >>= 1) {
            s += __shfl_xor_sync(0xffffffffu, s, off);
            q += __shfl_xor_sync(0xffffffffu, q, off);
        }
        if (lane == 0) {
            float mu = s * (1.f / 256.f);
            smean[row] = mu;
            srstd[row] = rsqrtf(q * (1.f / 256.f) - mu * mu + LN_EPS);
        }
    }
    __syncthreads();

    {
        int cl = (tid & 63) * 4;
        int rb = tid >> 6;
        float4 g4 = *(const float4*)&lng[cl];
        float4 b4 = *(const float4*)&lnb[cl];
        int h = cl >> 6, cc = cl & 63;
        const float qscale = 0.125f * LOG2E_;
        long long obase = ((long long)(b * NH_ + h) * DZ_ + z) * HW_;
        for (int r = rb; r < 64; r += 4) {
            float mu = smean[r], rs = srstd[r];
            float v0 = ((s_o[r * 260 + cl] - mu) * rs * g4.x + b4.x) * qscale;
            float v1 = ((s_o[r * 260 + cl + 1] - mu) * rs * g4.y + b4.y) * qscale;
            float v2 = ((s_o[r * 260 + cl + 2] - mu) * rs * g4.z + b4.z) * qscale;
            float v3 = ((s_o[r * 260 + cl + 3] - mu) * rs * g4.w + b4.w) * qscale;
            uint2 u = make_uint2(pk2(v0, v1), pk2(v2, v3));
            *(uint2*)&g_Q[(obase + p0 + r) * HD_ + cc] = u;
        }
    }
}

__device__ void kvproj_body(int job, const float* __restrict__ F2,
                            const float* __restrict__ lng,
                            const float* __restrict__ lnb, float* ksm) {
    float* xk = ksm;                  // [96][72]
    float* bs = ksm + 96 * 72;        // [256][33]
    float* s_o = ksm;                 // alias at base (xk/bs dead post-mma)
    __shared__ float smean[64], srstd[64];

    int mat = job & 1;
    int sp = job >> 1;
    int p0 = (sp % 9) * 64;
    int k = (sp / 9) % K_;
    int b = sp / (9 * K_);

    int tid = threadIdx.x;
    int w = tid >> 5, lane = tid & 31;
    int g = lane >> 2, t = lane & 3;
    int mt = w & 3, nh = w >> 2;

    {
        int r = tid & 63;
        int cb = tid >> 6;
        for (int c = cb; c < C2_; c += 4)
            xk[c * 72 + r] = F2[((b * C2_ + c) * HW_ + p0 + r) * K_ + k];
    }

    const float* WT = mat == 0 ? g_WkT : g_WvT;
    float4 acc[16];
#pragma unroll
    for (int n = 0; n < 16; n++) acc[n] = make_float4(0.f, 0.f, 0.f, 0.f);

    for (int kb = 0; kb < 3; kb++) {
        __syncthreads();
        {
            int kk = tid & 31;
            int n0 = tid >> 5;
            for (int n = n0; n < 256; n += 8)
                bs[n * 33 + kk] = WT[n * C2_ + kb * 32 + kk];
        }
        __syncthreads();
#pragma unroll
        for (int kcl = 0; kcl < 4; kcl++) {
            int krow = kb * 32 + kcl * 8;
            int arow = mt * 16 + g;
            unsigned a0 = __float_as_uint(xk[(krow + t) * 72 + arow]);
            unsigned a1 = __float_as_uint(xk[(krow + t) * 72 + arow + 8]);
            unsigned a2 = __float_as_uint(xk[(krow + t + 4) * 72 + arow]);
            unsigned a3 = __float_as_uint(xk[(krow + t + 4) * 72 + arow + 8]);
#pragma unroll
            for (int n = 0; n < 16; n++) {
                const float* br = &bs[(nh * 128 + n * 8 + g) * 33 + kcl * 8];
                mma_tf32(acc[n], a0, a1, a2, a3,
                         __float_as_uint(br[t]), __float_as_uint(br[t + 4]));
            }
        }
    }
    __syncthreads();
    {
        int rl = mt * 16 + g;
#pragma unroll
        for (int n = 0; n < 16; n++) {
            int col = nh * 128 + n * 8 + 2 * t;
            s_o[rl * 260 + col] = acc[n].x;
            s_o[rl * 260 + col + 1] = acc[n].y;
            s_o[(rl + 8) * 260 + col] = acc[n].z;
            s_o[(rl + 8) * 260 + col + 1] = acc[n].w;
        }
    }
    __syncthreads();
#pragma unroll
    for (int rr = 0; rr < 8; rr++) {
        int row = w * 8 + rr;
        float s = 0.f, q = 0.f;
#pragma unroll
        for (int jj = 0; jj < 8; jj++) {
            float v = s_o[row * 260 + lane + 32 * jj];
            s += v; q += v * v;
        }
#pragma unroll
        for (int off = 16; off >= 1; off >>= 1) {
            s += __shfl_xor_sync(0xffffffffu, s, off);
            q += __shfl_xor_sync(0xffffffffu, q, off);
        }
        if (lane == 0) {
            float mu = s * (1.f / 256.f);
            smean[row] = mu;
            srstd[row] = rsqrtf(q * (1.f / 256.f) - mu * mu + LN_EPS);
        }
    }
    __syncthreads();

    if (mat == 0) {
        int cl = (tid & 63) * 4;
        int rb = tid >> 6;
        float4 g4 = *(const float4*)&lng[cl];
        float4 b4 = *(const float4*)&lnb[cl];
        int h = cl >> 6, cc = cl & 63;
        long long obase = ((long long)(b * NH_ + h) * K_ + k) * HW_;
        for (int r = rb; r < 64; r += 4) {
            float mu = smean[r], rs = srstd[r];
            float v0 = (s_o[r * 260 + cl] - mu) * rs * g4.x + b4.x;
            float v1 = (s_o[r * 260 + cl + 1] - mu) * rs * g4.y + b4.y;
            float v2 = (s_o[r * 260 + cl + 2] - mu) * rs * g4.z + b4.z;
            float v3 = (s_o[r * 260 + cl + 3] - mu) * rs * g4.w + b4.w;
            uint2 u = make_uint2(pk2(v0, v1), pk2(v2, v3));
            *(uint2*)&g_K[(obase + p0 + r) * HD_ + cc] = u;
        }
    } else {
        int e = tid;
        float ge = lng[e], be = lnb[e];
        int h = e >> 6, d = e & 63;
        long long vb = (((long long)(b * NH_ + h) * K_ + k) * HD_ + d) * HW_ + p0;
#pragma unroll
        for (int rb2 = 0; rb2 < 16; rb2++) {
            int r = rb2 * 4;
            float v0 = (s_o[r * 260 + e] - smean[r]) * srstd[r] * ge + be;
            float v1 = (s_o[(r + 1) * 260 + e] - smean[r + 1]) * srstd[r + 1] * ge + be;
            float v2 = (s_o[(r + 2) * 260 + e] - smean[r + 2]) * srstd[r + 2] * ge + be;
            float v3 = (s_o[(r + 3) * 260 + e] - smean[r + 3]) * srstd[r + 3] * ge + be;
            uint2 u = make_uint2(pkh(v0, v1), pkh(v2, v3));   // fp16 V
            *(uint2*)&g_Vt[vb + r] = u;
        }
    }
}

#define NJ_CONV 96
#define NJ_Q 576
#define NJ_KV 288
__global__ __launch_bounds__(256) void k_front(const float* __restrict__ F2,
                                               const float* __restrict__ F3,
                                               const float* __restrict__ bng,
                                               const float* __restrict__ bnb,
                                               const float* __restrict__ lnkg,
                                               const float* __restrict__ lnkb,
                                               const float* __restrict__ lnqg,
                                               const float* __restrict__ lnqb) {
    extern __shared__ float fsm[];
    int job = blockIdx.x;
    if (job < NJ_CONV) {
        conv1_body(job, F2, bng, bnb, fsm);
    } else if (job < NJ_CONV + NJ_Q) {
        qproj_body(job - NJ_CONV, F3, lnqg, lnqb, fsm);
    } else {
        kvproj_body(job - NJ_CONV - NJ_Q, F2, lnkg, lnkb, fsm);
    }
}

// ------------------- kernel 2: conv2 1x1 + neighbor-sum -> topo -------------
__global__ __launch_bounds__(192) void k_topo(const float* __restrict__ w2,
                                              const float* __restrict__ w2b) {
    __shared__ float sp[HW_];
    __shared__ float wsh[64];
    int bk = blockIdx.x;
    int tid = threadIdx.x;
    if (tid < 64) wsh[tid] = w2[tid];
    __syncthreads();
    for (int p = tid; p < HW_; p += 192) {
        const float* hp = &g_h[(bk * HW_ + p) * TOPO_];
        float s = w2b[0];
#pragma unroll
        for (int o = 0; o < 64; o += 4) {
            float4 hv = *(const float4*)&hp[o];
            s += hv.x * wsh[o] + hv.y * wsh[o + 1] + hv.z * wsh[o + 2] + hv.w * wsh[o + 3];
        }
        sp[p] = s;
    }
    __syncthreads();
    for (int p = tid; p < HW_; p += 192) {
        int y = p / 24, x = p % 24;
        float s = 0.f;
#pragma unroll
        for (int dy = -1; dy <= 1; dy++)
#pragma unroll
            for (int dx = -1; dx <= 1; dx++) {
                if (dy == 0 && dx == 0) continue;
                int yy = y + dy, xx = x + dx;
                if ((unsigned)yy < 24u && (unsigned)xx < 24u) s += sp[yy * 24 + xx];
            }
        g_topo[bk * HW_ + p] = sp[p] + 0.5f * s;
    }
}

// ------ kernel 5: flash attention (bf16 S-mma, f16x2 exp, f16 PV-mma) -------
// R11 best-known configuration: 128 threads, 2 z/block, 64-key tiles, BST=72.
#define BST 72
__global__ __launch_bounds__(128) void k_attn(const float* __restrict__ lam_p,
                                              const void* __restrict__ D0_p,
                                              const void* __restrict__ slab_p) {
    extern __shared__ __nv_bfloat16 bsm[];
    __nv_bfloat16* Qs = bsm;                   // [128][BST]
    __nv_bfloat16* Ks = bsm + 128 * BST;       // [64][BST]
    __half* Vs = (__half*)(bsm + 192 * BST);   // [64][BST] fp16

    int bid = blockIdx.x;
    int p0 = (bid % 9) * 64;
    int zp = (bid / 9) % (DZ_ / 2);
    int h = (bid / (9 * (DZ_ / 2))) % NH_;
    int b = bid / (9 * (DZ_ / 2) * NH_);
    int z0 = zp * 2;

    int D0 = flex_int(D0_p, 128);
    int slab = flex_int(slab_p, 16);
    float lam2 = (*lam_p) * LOG2E_;

    int kkz[2], cloz[2], chiz[2];
#pragma unroll
    for (int i = 0; i < 2; i++) {
        int zz = z0 + i;
        int zq = (int)llrint((double)(D0 - 1) * (double)zz / (double)(DZ_ - 1));
        int kk = zq / slab;
        if (kk < 0) kk = 0;
        if (kk > K_ - 1) kk = K_ - 1;
        kkz[i] = kk;
        cloz[i] = (kk - 1 < 0) ? 0 : kk - 1;
        chiz[i] = (kk + 1 > K_ - 1) ? K_ - 1 : kk + 1;
    }
    int cU_lo = min(cloz[0], cloz[1]);
    int cU_hi = max(chiz[0], chiz[1]);

    int tid = threadIdx.x;
    int w = tid >> 5;
    int lane = tid & 31;
    int g = lane >> 2;
    int t = lane & 3;

    int wz = w >> 1;
    int zw = z0 + wz;
    int kk_w = kkz[wz], clo_w = cloz[wz], chi_w = chiz[wz];
    int prow = p0 + (w & 1) * 32;
    int qrow = w * 32;

    unsigned qb_s = (unsigned)__cvta_generic_to_shared(Qs);
    unsigned kb_s = (unsigned)__cvta_generic_to_shared(Ks);
    unsigned vb_s = (unsigned)__cvta_generic_to_shared(Vs);
    unsigned laneoff = (((lane & 7) + ((lane >> 3) & 1) * 8) * BST + ((lane >> 4) & 1) * 8) * 2;

    {
        long long qb0 = ((((long long)(b * NH_ + h) * DZ_ + z0) * HW_) + p0) * HD_;
#pragma unroll
        for (int it = 0; it < 8; it++) {
            int idx = tid + it * 128;
            int r = idx >> 3, v = (idx & 7) * 8;
            long long src = qb0 + (long long)(r >> 6) * (HW_ * HD_) + (long long)(r & 63) * 64 + v;
            *(uint4*)&Qs[r * BST + v] = *(const uint4*)&g_Q[src];
        }
    }

    float4 lacc0 = make_float4(0.f, 0.f, 0.f, 0.f);
    float4 lacc1 = make_float4(0.f, 0.f, 0.f, 0.f);
    float4 O0[8], O1[8];
#pragma unroll
    for (int n = 0; n < 8; n++) {
        O0[n] = make_float4(0.f, 0.f, 0.f, 0.f);
        O1[n] = make_float4(0.f, 0.f, 0.f, 0.f);
    }

    for (int c = cU_lo; c <= cU_hi; c++) {
        bool active = (c >= clo_w) && (c <= chi_w);
        float bias2 = (c == kk_w) ? 0.f : -0.5f * LOG2E_;
        long long kb = (((long long)(b * NH_ + h) * K_ + c) * HW_) * HD_;
        long long vb = (((long long)(b * NH_ + h) * K_ + c) * HD_) * HW_;
        const float* topo_c = &g_topo[(b * K_ + c) * HW_];
        for (int pk0 = 0; pk0 < HW_; pk0 += 64) {
            __syncthreads();
#pragma unroll
            for (int it = 0; it < 4; it++) {
                int idx = tid + it * 128;
                int r = idx >> 3, v = (idx & 7) * 8;
                *(uint4*)&Ks[r * BST + v] = *(const uint4*)&g_K[kb + (long long)(pk0 + r) * 64 + v];
                *(uint4*)&Vs[r * BST + v] = *(const uint4*)&g_Vt[vb + (long long)r * HW_ + pk0 + v];
            }
            __syncthreads();
            if (!active) continue;

            // ---- S = Q*K^T (bf16) ----
            float4 S0[8], S1[8];
#pragma unroll
            for (int n = 0; n < 8; n++) {
                S0[n] = make_float4(0.f, 0.f, 0.f, 0.f);
                S1[n] = make_float4(0.f, 0.f, 0.f, 0.f);
            }
#pragma unroll
            for (int kc = 0; kc < 4; kc++) {
                int kc16 = kc * 16;
                unsigned a00, a01, a02, a03, a10, a11, a12, a13;
                ldsm4(a00, a01, a02, a03, qb_s + (qrow * BST + kc16) * 2 + laneoff);
                ldsm4(a10, a11, a12, a13, qb_s + ((qrow + 16) * BST + kc16) * 2 + laneoff);
#pragma unroll
                for (int n2 = 0; n2 < 4; n2++) {
                    unsigned b0, b1, b2, b3;
                    ldsm4(b0, b1, b2, b3, kb_s + ((n2 * 16) * BST + kc16) * 2 + laneoff);
                    mma_bf16(S0[2 * n2],     a00, a01, a02, a03, b0, b2);
                    mma_bf16(S0[2 * n2 + 1], a00, a01, a02, a03, b1, b3);
                    mma_bf16(S1[2 * n2],     a10, a11, a12, a13, b0, b2);
                    mma_bf16(S1[2 * n2 + 1], a10, a11, a12, a13, b1, b3);
                }
            }

            // ---- bias (+ diagonal topo only when pixel tiles coincide) ----
            if (pk0 == p0) {
                int rq0 = prow + g;
                int rq1 = prow + 16 + g;
#pragma unroll
                for (int n = 0; n < 8; n++) {
                    int j0 = pk0 + n * 8 + 2 * t;
                    int j1 = j0 + 1;
                    float d00 = bias2, d01 = bias2, d02 = bias2, d03 = bias2;
                    float d10 = bias2, d11 = bias2, d12 = bias2, d13 = bias2;
                    if (rq0 == j0)     d00 += lam2 * topo_c[j0];
                    if (rq0 == j1)     d01 += lam2 * topo_c[j1];
                    if (rq0 + 8 == j0) d02 += lam2 * topo_c[j0];
                    if (rq0 + 8 == j1) d03 += lam2 * topo_c[j1];
                    if (rq1 == j0)     d10 += lam2 * topo_c[j0];
                    if (rq1 == j1)     d11 += lam2 * topo_c[j1];
                    if (rq1 + 8 == j0) d12 += lam2 * topo_c[j0];
                    if (rq1 + 8 == j1) d13 += lam2 * topo_c[j1];
                    S0[n].x += d00; S0[n].y += d01; S0[n].z += d02; S0[n].w += d03;
                    S1[n].x += d10; S1[n].y += d11; S1[n].z += d12; S1[n].w += d13;
                }
            } else {
#pragma unroll
                for (int n = 0; n < 8; n++) {
                    S0[n].x += bias2; S0[n].y += bias2; S0[n].z += bias2; S0[n].w += bias2;
                    S1[n].x += bias2; S1[n].y += bias2; S1[n].z += bias2; S1[n].w += bias2;
                }
            }

            // ---- P = exp2(S) in packed fp16; O += P*V; l via ones-mma ----
#pragma unroll
            for (int kc = 0; kc < 4; kc++) {
                int kc16 = kc * 16;
                unsigned a00 = ex2h(pkh(S0[2 * kc].x, S0[2 * kc].y));
                unsigned a01 = ex2h(pkh(S0[2 * kc].z, S0[2 * kc].w));
                unsigned a02 = ex2h(pkh(S0[2 * kc + 1].x, S0[2 * kc + 1].y));
                unsigned a03 = ex2h(pkh(S0[2 * kc + 1].z, S0[2 * kc + 1].w));
                unsigned a10 = ex2h(pkh(S1[2 * kc].x, S1[2 * kc].y));
                unsigned a11 = ex2h(pkh(S1[2 * kc].z, S1[2 * kc].w));
                unsigned a12 = ex2h(pkh(S1[2 * kc + 1].x, S1[2 * kc + 1].y));
                unsigned a13 = ex2h(pkh(S1[2 * kc + 1].z, S1[2 * kc + 1].w));
                mma_f16(lacc0, a00, a01, a02, a03, ONESH, ONESH);
                mma_f16(lacc1, a10, a11, a12, a13, ONESH, ONESH);
#pragma unroll
                for (int n2 = 0; n2 < 4; n2++) {
                    unsigned b0, b1, b2, b3;
                    ldsm4(b0, b1, b2, b3, vb_s + ((n2 * 16) * BST + kc16) * 2 + laneoff);
                    mma_f16(O0[2 * n2],     a00, a01, a02, a03, b0, b2);
                    mma_f16(O0[2 * n2 + 1], a00, a01, a02, a03, b1, b3);
                    mma_f16(O1[2 * n2],     a10, a11, a12, a13, b0, b2);
                    mma_f16(O1[2 * n2 + 1], a10, a11, a12, a13, b1, b3);
                }
            }
        }
    }

    float i00 = 1.f / lacc0.x, i01 = 1.f / lacc0.z;
    float i10 = 1.f / lacc1.x, i11 = 1.f / lacc1.z;
    long long ob = ((long long)(b * DZ_ + zw) * HW_) * E_ + h * HD_;
    int rq0 = prow + g, rq1 = prow + 16 + g;
#pragma unroll
    for (int n = 0; n < 8; n++) {
        int col = n * 8 + 2 * t;
        *(float2*)&g_O[ob + (long long)rq0 * E_ + col] = make_float2(O0[n].x * i00, O0[n].y * i00);
        *(float2*)&g_O[ob + (long long)(rq0 + 8) * E_ + col] = make_float2(O0[n].z * i01, O0[n].w * i01);
        *(float2*)&g_O[ob + (long long)rq1 * E_ + col] = make_float2(O1[n].x * i10, O1[n].y * i10);
        *(float2*)&g_O[ob + (long long)(rq1 + 8) * E_ + col] = make_float2(O1[n].z * i11, O1[n].w * i11);
    }
}

// ------------------- kernel 6: output projection + residual (tf32 MMA) ------
__global__ __launch_bounds__(256) void k_oproj(const float* __restrict__ F3,
                                               float* __restrict__ out) {
    extern __shared__ float osm[];
    float* bs = osm;                  // [128][33]
    float* s_o = osm + 128 * 33;      // [128 cols][68 rows]
    int bid = blockIdx.x;
    int p0 = (bid % 9) * 64;
    int z = (bid / 9) % DZ_;
    int b = bid / (9 * DZ_);

    int tid = threadIdx.x;
    int w = tid >> 5, lane = tid & 31;
    int g = lane >> 2, t = lane & 3;
    int mt = w & 3, nh = w >> 2;

    int rowl = (b * DZ_ + z) * HW_ + p0 + mt * 16 + g;
    const float* Al = &g_O[(long long)rowl * E_];
    const float* Ah = Al + 8LL * E_;

    float4 acc[8];
#pragma unroll
    for (int n = 0; n < 8; n++) acc[n] = make_float4(0.f, 0.f, 0.f, 0.f);

    for (int kb = 0; kb < 8; kb++) {
        __syncthreads();
        {
            int kk = tid & 31;
            int n0 = tid >> 5;
            for (int n = n0; n < 128; n += 8)
                bs[n * 33 + kk] = g_WpT[n * E_ + kb * 32 + kk];
        }
        __syncthreads();
#pragma unroll
        for (int kcl = 0; kcl < 4; kcl++) {
            int kcol = kb * 32 + kcl * 8;
            unsigned a0 = __float_as_uint(Al[kcol + t]);
            unsigned a1 = __float_as_uint(Ah[kcol + t]);
            unsigned a2 = __float_as_uint(Al[kcol + t + 4]);
            unsigned a3 = __float_as_uint(Ah[kcol + t + 4]);
#pragma unroll
            for (int n = 0; n < 8; n++) {
                const float* br = &bs[(nh * 64 + n * 8 + g) * 33 + kcl * 8];
                mma_tf32(acc[n], a0, a1, a2, a3,
                         __float_as_uint(br[t]), __float_as_uint(br[t + 4]));
            }
        }
    }
    __syncthreads();

    {
        int rl = mt * 16 + g;
#pragma unroll
        for (int n = 0; n < 8; n++) {
            int col = nh * 64 + n * 8 + 2 * t;
            s_o[col * 68 + rl] = acc[n].x;
            s_o[(col + 1) * 68 + rl] = acc[n].y;
            s_o[col * 68 + rl + 8] = acc[n].z;
            s_o[(col + 1) * 68 + rl + 8] = acc[n].w;
        }
    }
    __syncthreads();

    {
        int r = tid & 63;
        int cb = tid >> 6;
        for (int c = cb; c < C3_; c += 4) {
            long long oi = (long long)(b * C3_ + c) * (DZ_ * HW_) + z * HW_ + p0 + r;
            out[oi] = F3[oi] + s_o[c * 68 + r];
        }
    }
}

// ----------------------------------- launch ---------------------------------
extern "C" void kernel_launch(void* const* d_in, const int* in_sizes, int n_in,
                              void* d_out, int out_size) {
    const float* F3  = (const float*)d_in[0];
    const float* F2  = (const float*)d_in[1];
    const float* Wq  = (const float*)d_in[2];
    const float* Wk  = (const float*)d_in[3];
    const float* Wv  = (const float*)d_in[4];
    const float* Wp  = (const float*)d_in[5];
    const float* lnqg = (const float*)d_in[6];
    const float* lnqb = (const float*)d_in[7];
    const float* lnkg = (const float*)d_in[8];
    const float* lnkb = (const float*)d_in[9];
    const float* w1   = (const float*)d_in[10];
    const float* bng  = (const float*)d_in[11];
    const float* bnb  = (const float*)d_in[12];
    const float* w2   = (const float*)d_in[13];
    const float* w2b  = (const float*)d_in[14];
    const float* lam  = (const float*)d_in[15];
    const void*  D0p  = d_in[16];
    const void*  slabp = d_in[17];
    float* out = (float*)d_out;

    int front_smem = (128 * 72 + 256 * 33) * (int)sizeof(float);    // 70656 (qproj max)
    int attn_smem  = 256 * BST * (int)sizeof(__nv_bfloat16);        // 36864
    int oproj_smem = (128 * 33 + 128 * 68) * (int)sizeof(float);    // 51712
    static int cfg_done = 0;
    if (!cfg_done) {
        cudaFuncSetAttribute(k_front, cudaFuncAttributeMaxDynamicSharedMemorySize, front_smem);
        cudaFuncSetAttribute(k_attn, cudaFuncAttributeMaxDynamicSharedMemorySize, attn_smem);
        cudaFuncSetAttribute(k_oproj, cudaFuncAttributeMaxDynamicSharedMemorySize, oproj_smem);
        cfg_done = 1;
    }

    k_wprep<<<(TOPO_ * C2_ * 9 + 255) / 256, 256>>>(w1, Wq, Wp, Wk, Wv);
    k_front<<<NJ_CONV + NJ_Q + NJ_KV, 256, front_smem>>>(F2, F3, bng, bnb,
                                                         lnkg, lnkb, lnqg, lnqb);
    k_topo<<<B_ * K_, 192>>>(w2, w2b);
    k_attn<<<B_ * NH_ * (DZ_ / 2) * 9, 128, attn_smem>>>(lam, D0p, slabp);
    k_oproj<<<B_ * DZ_ * 9, 256, oproj_smem>>>(F3, out);
}

// round 16
// speedup vs baseline: 1.5586x; 1.0055x over previous
#include <cuda_runtime.h>
#include <cuda_bf16.h>
#include <cuda_fp16.h>
#include <math.h>

#define B_ 2
#define C3_ 128
#define DZ_ 32
#define HW_ 576
#define C2_ 96
#define K_ 8
#define E_ 256
#define NH_ 4
#define HD_ 64
#define TOPO_ 64
#define LN_EPS 1e-5f
#define LOG2E_ 1.4426950408889634f
#define ONESH 0x3C003C00u   // fp16 {1.0, 1.0}

// ------------------------- device scratch (no allocation) -------------------
__device__ float g_w1t[C2_ * 9 * TOPO_];
__device__ float g_h[B_ * K_ * HW_ * TOPO_];
__device__ float g_topo[B_ * K_ * HW_];
__device__ __nv_bfloat16 g_Q[B_ * NH_ * DZ_ * HW_ * HD_];   // pre-scaled by log2e/8
__device__ __nv_bfloat16 g_K[B_ * NH_ * K_ * HW_ * HD_];    // (b,h,c,p,d)
__device__ __half g_Vt[B_ * NH_ * K_ * HD_ * HW_];          // (b,h,c,d,p) fp16, transposed
__device__ __half g_O[B_ * DZ_ * HW_ * E_];                 // fp16 attention output
__device__ float g_WqT[E_ * C3_];
__device__ float g_WpT[C3_ * E_];
__device__ float g_WkT[E_ * C2_];
__device__ float g_WvT[E_ * C2_];

__device__ __forceinline__ int flex_int(const void* p, int dflt) {
    int v = *(const int*)p;
    if (v >= 1 && v <= 1000000) return v;
    float f = *(const float*)p;
    if (f >= 1.f && f <= 1000000.f) return (int)f;
    return dflt;
}

__device__ __forceinline__ unsigned pk2(float lo, float hi) {          // bf16x2
    unsigned r;
    asm("cvt.rn.bf16x2.f32 %0, %1, %2;" : "=r"(r) : "f"(hi), "f"(lo));
    return r;
}

__device__ __forceinline__ unsigned pkh(float lo, float hi) {          // f16x2
    unsigned r;
    asm("cvt.rn.f16x2.f32 %0, %1, %2;" : "=r"(r) : "f"(hi), "f"(lo));
    return r;
}

__device__ __forceinline__ unsigned ex2h(unsigned x) {                 // exp2 on f16x2
    unsigned y;
    asm("ex2.approx.f16x2 %0, %1;" : "=r"(y) : "r"(x));
    return y;
}

__device__ __forceinline__ void ldsm4(unsigned& r0, unsigned& r1,
                                      unsigned& r2, unsigned& r3, unsigned addr) {
    asm volatile("ldmatrix.sync.aligned.m8n8.x4.shared.b16 {%0,%1,%2,%3}, [%4];"
                 : "=r"(r0), "=r"(r1), "=r"(r2), "=r"(r3) : "r"(addr));
}

__device__ __forceinline__ void mma_tf32(float4& d,
                                         unsigned a0, unsigned a1, unsigned a2, unsigned a3,
                                         unsigned b0, unsigned b1) {
    asm volatile(
        "mma.sync.aligned.m16n8k8.row.col.f32.tf32.tf32.f32 "
        "{%0,%1,%2,%3}, {%4,%5,%6,%7}, {%8,%9}, {%0,%1,%2,%3};"
        : "+f"(d.x), "+f"(d.y), "+f"(d.z), "+f"(d.w)
        : "r"(a0), "r"(a1), "r"(a2), "r"(a3), "r"(b0), "r"(b1));
}

__device__ __forceinline__ void mma_bf16(float4& d,
                                         unsigned a0, unsigned a1, unsigned a2, unsigned a3,
                                         unsigned b0, unsigned b1) {
    asm volatile(
        "mma.sync.aligned.m16n8k16.row.col.f32.bf16.bf16.f32 "
        "{%0,%1,%2,%3}, {%4,%5,%6,%7}, {%8,%9}, {%0,%1,%2,%3};"
        : "+f"(d.x), "+f"(d.y), "+f"(d.z), "+f"(d.w)
        : "r"(a0), "r"(a1), "r"(a2), "r"(a3), "r"(b0), "r"(b1));
}

__device__ __forceinline__ void mma_f16(float4& d,
                                        unsigned a0, unsigned a1, unsigned a2, unsigned a3,
                                        unsigned b0, unsigned b1) {
    asm volatile(
        "mma.sync.aligned.m16n8k16.row.col.f32.f16.f16.f32 "
        "{%0,%1,%2,%3}, {%4,%5,%6,%7}, {%8,%9}, {%0,%1,%2,%3};"
        : "+f"(d.x), "+f"(d.y), "+f"(d.z), "+f"(d.w)
        : "r"(a0), "r"(a1), "r"(a2), "r"(a3), "r"(b0), "r"(b1));
}

// ------------------------- kernel 0: all weight prep ------------------------
__global__ void k_wprep(const float* __restrict__ w1,
                        const float* __restrict__ Wq, const float* __restrict__ Wp,
                        const float* __restrict__ Wk, const float* __restrict__ Wv) {
    int i = blockIdx.x * 256 + threadIdx.x;
    if (i < TOPO_ * C2_ * 9) {
        int o = i / (C2_ * 9);
        int r = i % (C2_ * 9);
        int c = r / 9, tap = r % 9;
        g_w1t[(c * 9 + tap) * TOPO_ + o] = w1[i];
    }
    if (i < C3_ * E_) {
        int e = i / C3_, c = i % C3_;
        g_WqT[i] = Wq[c * E_ + e];
        g_WpT[c * E_ + e] = Wp[i];
    }
    if (i < C2_ * E_) {
        int e = i / C2_, c = i % C2_;
        g_WkT[i] = Wk[c * E_ + e];
        g_WvT[i] = Wv[c * E_ + e];
    }
}

// ===================== fused front: conv1 | qproj | kvproj ==================
__device__ void conv1_body(int job, const float* __restrict__ F2,
                           const float* __restrict__ bng,
                           const float* __restrict__ bnb, float* sm) {
    float* in_s = sm;            // [16][6][26]
    float* w_s = sm + 2496;      // [16*9*64]
    int bk = job / 6;
    int y0 = (job % 6) * 4;
    int b = bk >> 3, k = bk & 7;
    int tid = threadIdx.x;
    int pg = tid >> 3;
    int og = tid & 7;
    int pl = pg * 3;
    int yrel = pl / 24;
    int x0 = pl % 24;
    int o0 = og * 8;
    float acc[3][8];
#pragma unroll
    for (int u = 0; u < 3; u++)
#pragma unroll
        for (int v = 0; v < 8; v++) acc[u][v] = 0.f;

    for (int c0 = 0; c0 < C2_; c0 += 16) {
        __syncthreads();
        for (int idx = tid; idx < 16 * 6 * 26; idx += 256) {
            int cc = idx / 156, rem = idx % 156;
            int yy = rem / 26, xx = rem % 26;
            int y = y0 - 1 + yy, x = xx - 1;
            float v = 0.f;
            if ((unsigned)y < 24u && (unsigned)x < 24u)
                v = F2[((b * C2_ + c0 + cc) * HW_ + y * 24 + x) * K_ + k];
            in_s[cc * 156 + yy * 26 + xx] = v;
        }
        for (int idx = tid; idx < 16 * 9 * 64; idx += 256)
            w_s[idx] = g_w1t[c0 * 9 * 64 + idx];
        __syncthreads();
        for (int cc = 0; cc < 16; cc++) {
#pragma unroll
            for (int dy = 0; dy < 3; dy++) {
                float rv[5];
#pragma unroll
                for (int u = 0; u < 5; u++) rv[u] = in_s[cc * 156 + (yrel + dy) * 26 + x0 + u];
#pragma unroll
                for (int dx = 0; dx < 3; dx++) {
                    const float* wp = &w_s[(cc * 9 + dy * 3 + dx) * 64 + o0];
                    float4 wa = *(const float4*)wp;
                    float4 wb = *(const float4*)(wp + 4);
#pragma unroll
                    for (int u = 0; u < 3; u++) {
                        float a = rv[u + dx];
                        acc[u][0] += a * wa.x; acc[u][1] += a * wa.y;
                        acc[u][2] += a * wa.z; acc[u][3] += a * wa.w;
                        acc[u][4] += a * wb.x; acc[u][5] += a * wb.y;
                        acc[u][6] += a * wb.z; acc[u][7] += a * wb.w;
                    }
                }
            }
        }
    }
    float invs = rsqrtf(1.f + LN_EPS);
    float sg[8], sb[8];
#pragma unroll
    for (int v = 0; v < 8; v++) { sg[v] = bng[o0 + v] * invs; sb[v] = bnb[o0 + v]; }
#pragma unroll
    for (int u = 0; u < 3; u++) {
        int p = (y0 + yrel) * 24 + x0 + u;
        float4 h0, h1;
        h0.x = fmaxf(acc[u][0] * sg[0] + sb[0], 0.f);
        h0.y = fmaxf(acc[u][1] * sg[1] + sb[1], 0.f);
        h0.z = fmaxf(acc[u][2] * sg[2] + sb[2], 0.f);
        h0.w = fmaxf(acc[u][3] * sg[3] + sb[3], 0.f);
        h1.x = fmaxf(acc[u][4] * sg[4] + sb[4], 0.f);
        h1.y = fmaxf(acc[u][5] * sg[5] + sb[5], 0.f);
        h1.z = fmaxf(acc[u][6] * sg[6] + sb[6], 0.f);
        h1.w = fmaxf(acc[u][7] * sg[7] + sb[7], 0.f);
        *(float4*)&g_h[(bk * HW_ + p) * TOPO_ + o0] = h0;
        *(float4*)&g_h[(bk * HW_ + p) * TOPO_ + o0 + 4] = h1;
    }
}

__device__ void qproj_body(int job, const float* __restrict__ F3,
                           const float* __restrict__ lng,
                           const float* __restrict__ lnb, float* qsm) {
    float* xk = qsm;                  // [128][72]
    float* bs = qsm + 128 * 72;       // [256][33]
    float* s_o = qsm;                 // alias, [64][260]
    __shared__ float smean[64], srstd[64];

    int p0 = (job % 9) * 64;
    int z = (job / 9) % DZ_;
    int b = job / (9 * DZ_);

    int tid = threadIdx.x;
    int w = tid >> 5, lane = tid & 31;
    int g = lane >> 2, t = lane & 3;
    int mt = w & 3, nh = w >> 2;

    {
        int r = tid & 63;
        int cb = tid >> 6;
        for (int c = cb; c < C3_; c += 4)
            xk[c * 72 + r] = F3[(b * C3_ + c) * (DZ_ * HW_) + z * HW_ + p0 + r];
    }

    float4 acc[16];
#pragma unroll
    for (int n = 0; n < 16; n++) acc[n] = make_float4(0.f, 0.f, 0.f, 0.f);

    for (int kb = 0; kb < 4; kb++) {
        __syncthreads();
        {
            int kk = tid & 31;
            int n0 = tid >> 5;
            for (int n = n0; n < 256; n += 8)
                bs[n * 33 + kk] = g_WqT[n * C3_ + kb * 32 + kk];
        }
        __syncthreads();
#pragma unroll
        for (int kcl = 0; kcl < 4; kcl++) {
            int krow = kb * 32 + kcl * 8;
            int arow = mt * 16 + g;
            unsigned a0 = __float_as_uint(xk[(krow + t) * 72 + arow]);
            unsigned a1 = __float_as_uint(xk[(krow + t) * 72 + arow + 8]);
            unsigned a2 = __float_as_uint(xk[(krow + t + 4) * 72 + arow]);
            unsigned a3 = __float_as_uint(xk[(krow + t + 4) * 72 + arow + 8]);
#pragma unroll
            for (int n = 0; n < 16; n++) {
                const float* br = &bs[(nh * 128 + n * 8 + g) * 33 + kcl * 8];
                mma_tf32(acc[n], a0, a1, a2, a3,
                         __float_as_uint(br[t]), __float_as_uint(br[t + 4]));
            }
        }
    }
    __syncthreads();

    {
        int rl = mt * 16 + g;
#pragma unroll
        for (int n = 0; n < 16; n++) {
            int col = nh * 128 + n * 8 + 2 * t;
            s_o[rl * 260 + col] = acc[n].x;
            s_o[rl * 260 + col + 1] = acc[n].y;
            s_o[(rl + 8) * 260 + col] = acc[n].z;
            s_o[(rl + 8) * 260 + col + 1] = acc[n].w;
        }
    }
    __syncthreads();

#pragma unroll
    for (int rr = 0; rr < 8; rr++) {
        int row = w * 8 + rr;
        float s = 0.f, q = 0.f;
#pragma unroll
        for (int jj = 0; jj < 8; jj++) {
            float v = s_o[row * 260 + lane + 32 * jj];
            s += v; q += v * v;
        }
#pragma unroll
        for (int off = 16; off >= 1; off >>= 1) {
            s += __shfl_xor_sync(0xffffffffu, s, off);
            q += __shfl_xor_sync(0xffffffffu, q, off);
        }
        if (lane == 0) {
            float mu = s * (1.f / 256.f);
            smean[row] = mu;
            srstd[row] = rsqrtf(q * (1.f / 256.f) - mu * mu + LN_EPS);
        }
    }
    __syncthreads();

    {
        int cl = (tid & 63) * 4;
        int rb = tid >> 6;
        float4 g4 = *(const float4*)&lng[cl];
        float4 b4 = *(const float4*)&lnb[cl];
        int h = cl >> 6, cc = cl & 63;
        const float qscale = 0.125f * LOG2E_;
        long long obase = ((long long)(b * NH_ + h) * DZ_ + z) * HW_;
        for (int r = rb; r < 64; r += 4) {
            float mu = smean[r], rs = srstd[r];
            float v0 = ((s_o[r * 260 + cl] - mu) * rs * g4.x + b4.x) * qscale;
            float v1 = ((s_o[r * 260 + cl + 1] - mu) * rs * g4.y + b4.y) * qscale;
            float v2 = ((s_o[r * 260 + cl + 2] - mu) * rs * g4.z + b4.z) * qscale;
            float v3 = ((s_o[r * 260 + cl + 3] - mu) * rs * g4.w + b4.w) * qscale;
            uint2 u = make_uint2(pk2(v0, v1), pk2(v2, v3));
            *(uint2*)&g_Q[(obase + p0 + r) * HD_ + cc] = u;
        }
    }
}

__device__ void kvproj_body(int job, const float* __restrict__ F2,
                            const float* __restrict__ lng,
                            const float* __restrict__ lnb, float* ksm) {
    float* xk = ksm;                  // [96][72]
    float* bs = ksm + 96 * 72;        // [256][33]
    float* s_o = ksm;                 // alias at base (xk/bs dead post-mma)
    __shared__ float smean[64], srstd[64];

    int mat = job & 1;
    int sp = job >> 1;
    int p0 = (sp % 9) * 64;
    int k = (sp / 9) % K_;
    int b = sp / (9 * K_);

    int tid = threadIdx.x;
    int w = tid >> 5, lane = tid & 31;
    int g = lane >> 2, t = lane & 3;
    int mt = w & 3, nh = w >> 2;

    {
        int r = tid & 63;
        int cb = tid >> 6;
        for (int c = cb; c < C2_; c += 4)
            xk[c * 72 + r] = F2[((b * C2_ + c) * HW_ + p0 + r) * K_ + k];
    }

    const float* WT = mat == 0 ? g_WkT : g_WvT;
    float4 acc[16];
#pragma unroll
    for (int n = 0; n < 16; n++) acc[n] = make_float4(0.f, 0.f, 0.f, 0.f);

    for (int kb = 0; kb < 3; kb++) {
        __syncthreads();
        {
            int kk = tid & 31;
            int n0 = tid >> 5;
            for (int n = n0; n < 256; n += 8)
                bs[n * 33 + kk] = WT[n * C2_ + kb * 32 + kk];
        }
        __syncthreads();
#pragma unroll
        for (int kcl = 0; kcl < 4; kcl++) {
            int krow = kb * 32 + kcl * 8;
            int arow = mt * 16 + g;
            unsigned a0 = __float_as_uint(xk[(krow + t) * 72 + arow]);
            unsigned a1 = __float_as_uint(xk[(krow + t) * 72 + arow + 8]);
            unsigned a2 = __float_as_uint(xk[(krow + t + 4) * 72 + arow]);
            unsigned a3 = __float_as_uint(xk[(krow + t + 4) * 72 + arow + 8]);
#pragma unroll
            for (int n = 0; n < 16; n++) {
                const float* br = &bs[(nh * 128 + n * 8 + g) * 33 + kcl * 8];
                mma_tf32(acc[n], a0, a1, a2, a3,
                         __float_as_uint(br[t]), __float_as_uint(br[t + 4]));
            }
        }
    }
    __syncthreads();
    {
        int rl = mt * 16 + g;
#pragma unroll
        for (int n = 0; n < 16; n++) {
            int col = nh * 128 + n * 8 + 2 * t;
            s_o[rl * 260 + col] = acc[n].x;
            s_o[rl * 260 + col + 1] = acc[n].y;
            s_o[(rl + 8) * 260 + col] = acc[n].z;
            s_o[(rl + 8) * 260 + col + 1] = acc[n].w;
        }
    }
    __syncthreads();
#pragma unroll
    for (int rr = 0; rr < 8; rr++) {
        int row = w * 8 + rr;
        float s = 0.f, q = 0.f;
#pragma unroll
        for (int jj = 0; jj < 8; jj++) {
            float v = s_o[row * 260 + lane + 32 * jj];
            s += v; q += v * v;
        }
#pragma unroll
        for (int off = 16; off >= 1; off >>= 1) {
            s += __shfl_xor_sync(0xffffffffu, s, off);
            q += __shfl_xor_sync(0xffffffffu, q, off);
        }
        if (lane == 0) {
            float mu = s * (1.f / 256.f);
            smean[row] = mu;
            srstd[row] = rsqrtf(q * (1.f / 256.f) - mu * mu + LN_EPS);
        }
    }
    __syncthreads();

    if (mat == 0) {
        int cl = (tid & 63) * 4;
        int rb = tid >> 6;
        float4 g4 = *(const float4*)&lng[cl];
        float4 b4 = *(const float4*)&lnb[cl];
        int h = cl >> 6, cc = cl & 63;
        long long obase = ((long long)(b * NH_ + h) * K_ + k) * HW_;
        for (int r = rb; r < 64; r += 4) {
            float mu = smean[r], rs = srstd[r];
            float v0 = (s_o[r * 260 + cl] - mu) * rs * g4.x + b4.x;
            float v1 = (s_o[r * 260 + cl + 1] - mu) * rs * g4.y + b4.y;
            float v2 = (s_o[r * 260 + cl + 2] - mu) * rs * g4.z + b4.z;
            float v3 = (s_o[r * 260 + cl + 3] - mu) * rs * g4.w + b4.w;
            uint2 u = make_uint2(pk2(v0, v1), pk2(v2, v3));
            *(uint2*)&g_K[(obase + p0 + r) * HD_ + cc] = u;
        }
    } else {
        int e = tid;
        float ge = lng[e], be = lnb[e];
        int h = e >> 6, d = e & 63;
        long long vb = (((long long)(b * NH_ + h) * K_ + k) * HD_ + d) * HW_ + p0;
#pragma unroll
        for (int rb2 = 0; rb2 < 16; rb2++) {
            int r = rb2 * 4;
            float v0 = (s_o[r * 260 + e] - smean[r]) * srstd[r] * ge + be;
            float v1 = (s_o[(r + 1) * 260 + e] - smean[r + 1]) * srstd[r + 1] * ge + be;
            float v2 = (s_o[(r + 2) * 260 + e] - smean[r + 2]) * srstd[r + 2] * ge + be;
            float v3 = (s_o[(r + 3) * 260 + e] - smean[r + 3]) * srstd[r + 3] * ge + be;
            uint2 u = make_uint2(pkh(v0, v1), pkh(v2, v3));   // fp16 V
            *(uint2*)&g_Vt[vb + r] = u;
        }
    }
}

#define NJ_CONV 96
#define NJ_Q 576
#define NJ_KV 288
__global__ __launch_bounds__(256) void k_front(const float* __restrict__ F2,
                                               const float* __restrict__ F3,
                                               const float* __restrict__ bng,
                                               const float* __restrict__ bnb,
                                               const float* __restrict__ lnkg,
                                               const float* __restrict__ lnkb,
                                               const float* __restrict__ lnqg,
                                               const float* __restrict__ lnqb) {
    extern __shared__ float fsm[];
    int job = blockIdx.x;
    if (job < NJ_CONV) {
        conv1_body(job, F2, bng, bnb, fsm);
    } else if (job < NJ_CONV + NJ_Q) {
        qproj_body(job - NJ_CONV, F3, lnqg, lnqb, fsm);
    } else {
        kvproj_body(job - NJ_CONV - NJ_Q, F2, lnkg, lnkb, fsm);
    }
}

// ------------------- kernel 2: conv2 1x1 + neighbor-sum -> topo -------------
__global__ __launch_bounds__(192) void k_topo(const float* __restrict__ w2,
                                              const float* __restrict__ w2b) {
    __shared__ float sp[HW_];
    __shared__ float wsh[64];
    int bk = blockIdx.x;
    int tid = threadIdx.x;
    if (tid < 64) wsh[tid] = w2[tid];
    __syncthreads();
    for (int p = tid; p < HW_; p += 192) {
        const float* hp = &g_h[(bk * HW_ + p) * TOPO_];
        float s = w2b[0];
#pragma unroll
        for (int o = 0; o < 64; o += 4) {
            float4 hv = *(const float4*)&hp[o];
            s += hv.x * wsh[o] + hv.y * wsh[o + 1] + hv.z * wsh[o + 2] + hv.w * wsh[o + 3];
        }
        sp[p] = s;
    }
    __syncthreads();
    for (int p = tid; p < HW_; p += 192) {
        int y = p / 24, x = p % 24;
        float s = 0.f;
#pragma unroll
        for (int dy = -1; dy <= 1; dy++)
#pragma unroll
            for (int dx = -1; dx <= 1; dx++) {
                if (dy == 0 && dx == 0) continue;
                int yy = y + dy, xx = x + dx;
                if ((unsigned)yy < 24u && (unsigned)xx < 24u) s += sp[yy * 24 + xx];
            }
        g_topo[bk * HW_ + p] = sp[p] + 0.5f * s;
    }
}

// ------ kernel 5: flash attention (bf16 S-mma, f16x2 exp, f16 PV-mma) -------
// Locked best configuration: 128 threads, 2 z/block, 64-key tiles, BST=72.
#define BST 72
__global__ __launch_bounds__(128) void k_attn(const float* __restrict__ lam_p,
                                              const void* __restrict__ D0_p,
                                              const void* __restrict__ slab_p) {
    extern __shared__ __nv_bfloat16 bsm[];
    __nv_bfloat16* Qs = bsm;                   // [128][BST]
    __nv_bfloat16* Ks = bsm + 128 * BST;       // [64][BST]
    __half* Vs = (__half*)(bsm + 192 * BST);   // [64][BST] fp16

    int bid = blockIdx.x;
    int p0 = (bid % 9) * 64;
    int zp = (bid / 9) % (DZ_ / 2);
    int h = (bid / (9 * (DZ_ / 2))) % NH_;
    int b = bid / (9 * (DZ_ / 2) * NH_);
    int z0 = zp * 2;

    int D0 = flex_int(D0_p, 128);
    int slab = flex_int(slab_p, 16);
    float lam2 = (*lam_p) * LOG2E_;

    int kkz[2], cloz[2], chiz[2];
#pragma unroll
    for (int i = 0; i < 2; i++) {
        int zz = z0 + i;
        int zq = (int)llrint((double)(D0 - 1) * (double)zz / (double)(DZ_ - 1));
        int kk = zq / slab;
        if (kk < 0) kk = 0;
        if (kk > K_ - 1) kk = K_ - 1;
        kkz[i] = kk;
        cloz[i] = (kk - 1 < 0) ? 0 : kk - 1;
        chiz[i] = (kk + 1 > K_ - 1) ? K_ - 1 : kk + 1;
    }
    int cU_lo = min(cloz[0], cloz[1]);
    int cU_hi = max(chiz[0], chiz[1]);

    int tid = threadIdx.x;
    int w = tid >> 5;
    int lane = tid & 31;
    int g = lane >> 2;
    int t = lane & 3;

    int wz = w >> 1;
    int zw = z0 + wz;
    int kk_w = kkz[wz], clo_w = cloz[wz], chi_w = chiz[wz];
    int prow = p0 + (w & 1) * 32;
    int qrow = w * 32;

    unsigned qb_s = (unsigned)__cvta_generic_to_shared(Qs);
    unsigned kb_s = (unsigned)__cvta_generic_to_shared(Ks);
    unsigned vb_s = (unsigned)__cvta_generic_to_shared(Vs);
    unsigned laneoff = (((lane & 7) + ((lane >> 3) & 1) * 8) * BST + ((lane >> 4) & 1) * 8) * 2;

    {
        long long qb0 = ((((long long)(b * NH_ + h) * DZ_ + z0) * HW_) + p0) * HD_;
#pragma unroll
        for (int it = 0; it < 8; it++) {
            int idx = tid + it * 128;
            int r = idx >> 3, v = (idx & 7) * 8;
            long long src = qb0 + (long long)(r >> 6) * (HW_ * HD_) + (long long)(r & 63) * 64 + v;
            *(uint4*)&Qs[r * BST + v] = *(const uint4*)&g_Q[src];
        }
    }

    float4 lacc0 = make_float4(0.f, 0.f, 0.f, 0.f);
    float4 lacc1 = make_float4(0.f, 0.f, 0.f, 0.f);
    float4 O0[8], O1[8];
#pragma unroll
    for (int n = 0; n < 8; n++) {
        O0[n] = make_float4(0.f, 0.f, 0.f, 0.f);
        O1[n] = make_float4(0.f, 0.f, 0.f, 0.f);
    }

    for (int c = cU_lo; c <= cU_hi; c++) {
        bool active = (c >= clo_w) && (c <= chi_w);
        float bias2 = (c == kk_w) ? 0.f : -0.5f * LOG2E_;
        long long kb = (((long long)(b * NH_ + h) * K_ + c) * HW_) * HD_;
        long long vb = (((long long)(b * NH_ + h) * K_ + c) * HD_) * HW_;
        const float* topo_c = &g_topo[(b * K_ + c) * HW_];
        for (int pk0 = 0; pk0 < HW_; pk0 += 64) {
            __syncthreads();
#pragma unroll
            for (int it = 0; it < 4; it++) {
                int idx = tid + it * 128;
                int r = idx >> 3, v = (idx & 7) * 8;
                *(uint4*)&Ks[r * BST + v] = *(const uint4*)&g_K[kb + (long long)(pk0 + r) * 64 + v];
                *(uint4*)&Vs[r * BST + v] = *(const uint4*)&g_Vt[vb + (long long)r * HW_ + pk0 + v];
            }
            __syncthreads();
            if (!active) continue;

            // ---- S = Q*K^T (bf16) ----
            float4 S0[8], S1[8];
#pragma unroll
            for (int n = 0; n < 8; n++) {
                S0[n] = make_float4(0.f, 0.f, 0.f, 0.f);
                S1[n] = make_float4(0.f, 0.f, 0.f, 0.f);
            }
#pragma unroll
            for (int kc = 0; kc < 4; kc++) {
                int kc16 = kc * 16;
                unsigned a00, a01, a02, a03, a10, a11, a12, a13;
                ldsm4(a00, a01, a02, a03, qb_s + (qrow * BST + kc16) * 2 + laneoff);
                ldsm4(a10, a11, a12, a13, qb_s + ((qrow + 16) * BST + kc16) * 2 + laneoff);
#pragma unroll
                for (int n2 = 0; n2 < 4; n2++) {
                    unsigned b0, b1, b2, b3;
                    ldsm4(b0, b1, b2, b3, kb_s + ((n2 * 16) * BST + kc16) * 2 + laneoff);
                    mma_bf16(S0[2 * n2],     a00, a01, a02, a03, b0, b2);
                    mma_bf16(S0[2 * n2 + 1], a00, a01, a02, a03, b1, b3);
                    mma_bf16(S1[2 * n2],     a10, a11, a12, a13, b0, b2);
                    mma_bf16(S1[2 * n2 + 1], a10, a11, a12, a13, b1, b3);
                }
            }

            // ---- bias (+ diagonal topo only when pixel tiles coincide) ----
            if (pk0 == p0) {
                int rq0 = prow + g;
                int rq1 = prow + 16 + g;
#pragma unroll
                for (int n = 0; n < 8; n++) {
                    int j0 = pk0 + n * 8 + 2 * t;
                    int j1 = j0 + 1;
                    float d00 = bias2, d01 = bias2, d02 = bias2, d03 = bias2;
                    float d10 = bias2, d11 = bias2, d12 = bias2, d13 = bias2;
                    if (rq0 == j0)     d00 += lam2 * topo_c[j0];
                    if (rq0 == j1)     d01 += lam2 * topo_c[j1];
                    if (rq0 + 8 == j0) d02 += lam2 * topo_c[j0];
                    if (rq0 + 8 == j1) d03 += lam2 * topo_c[j1];
                    if (rq1 == j0)     d10 += lam2 * topo_c[j0];
                    if (rq1 == j1)     d11 += lam2 * topo_c[j1];
                    if (rq1 + 8 == j0) d12 += lam2 * topo_c[j0];
                    if (rq1 + 8 == j1) d13 += lam2 * topo_c[j1];
                    S0[n].x += d00; S0[n].y += d01; S0[n].z += d02; S0[n].w += d03;
                    S1[n].x += d10; S1[n].y += d11; S1[n].z += d12; S1[n].w += d13;
                }
            } else {
#pragma unroll
                for (int n = 0; n < 8; n++) {
                    S0[n].x += bias2; S0[n].y += bias2; S0[n].z += bias2; S0[n].w += bias2;
                    S1[n].x += bias2; S1[n].y += bias2; S1[n].z += bias2; S1[n].w += bias2;
                }
            }

            // ---- P = exp2(S) in packed fp16; O += P*V; l via ones-mma ----
#pragma unroll
            for (int kc = 0; kc < 4; kc++) {
                int kc16 = kc * 16;
                unsigned a00 = ex2h(pkh(S0[2 * kc].x, S0[2 * kc].y));
                unsigned a01 = ex2h(pkh(S0[2 * kc].z, S0[2 * kc].w));
                unsigned a02 = ex2h(pkh(S0[2 * kc + 1].x, S0[2 * kc + 1].y));
                unsigned a03 = ex2h(pkh(S0[2 * kc + 1].z, S0[2 * kc + 1].w));
                unsigned a10 = ex2h(pkh(S1[2 * kc].x, S1[2 * kc].y));
                unsigned a11 = ex2h(pkh(S1[2 * kc].z, S1[2 * kc].w));
                unsigned a12 = ex2h(pkh(S1[2 * kc + 1].x, S1[2 * kc + 1].y));
                unsigned a13 = ex2h(pkh(S1[2 * kc + 1].z, S1[2 * kc + 1].w));
                mma_f16(lacc0, a00, a01, a02, a03, ONESH, ONESH);
                mma_f16(lacc1, a10, a11, a12, a13, ONESH, ONESH);
#pragma unroll
                for (int n2 = 0; n2 < 4; n2++) {
                    unsigned b0, b1, b2, b3;
                    ldsm4(b0, b1, b2, b3, vb_s + ((n2 * 16) * BST + kc16) * 2 + laneoff);
                    mma_f16(O0[2 * n2],     a00, a01, a02, a03, b0, b2);
                    mma_f16(O0[2 * n2 + 1], a00, a01, a02, a03, b1, b3);
                    mma_f16(O1[2 * n2],     a10, a11, a12, a13, b0, b2);
                    mma_f16(O1[2 * n2 + 1], a10, a11, a12, a13, b1, b3);
                }
            }
        }
    }

    float i00 = 1.f / lacc0.x, i01 = 1.f / lacc0.z;
    float i10 = 1.f / lacc1.x, i11 = 1.f / lacc1.z;
    long long ob = ((long long)(b * DZ_ + zw) * HW_) * E_ + h * HD_;
    int rq0 = prow + g, rq1 = prow + 16 + g;
#pragma unroll
    for (int n = 0; n < 8; n++) {
        int col = n * 8 + 2 * t;
        *(unsigned*)&g_O[ob + (long long)rq0 * E_ + col] = pkh(O0[n].x * i00, O0[n].y * i00);
        *(unsigned*)&g_O[ob + (long long)(rq0 + 8) * E_ + col] = pkh(O0[n].z * i01, O0[n].w * i01);
        *(unsigned*)&g_O[ob + (long long)rq1 * E_ + col] = pkh(O1[n].x * i10, O1[n].y * i10);
        *(unsigned*)&g_O[ob + (long long)(rq1 + 8) * E_ + col] = pkh(O1[n].z * i11, O1[n].w * i11);
    }
}

// ---- kernel 6: output projection + residual (tf32 MMA, fp16 A loads) -------
__global__ __launch_bounds__(256) void k_oproj(const float* __restrict__ F3,
                                               float* __restrict__ out) {
    extern __shared__ float osm[];
    float* bs = osm;                  // [128][33]
    float* s_o = osm + 128 * 33;      // [128 cols][68 rows]
    int bid = blockIdx.x;
    int p0 = (bid % 9) * 64;
    int z = (bid / 9) % DZ_;
    int b = bid / (9 * DZ_);

    int tid = threadIdx.x;
    int w = tid >> 5, lane = tid & 31;
    int g = lane >> 2, t = lane & 3;
    int mt = w & 3, nh = w >> 2;

    int rowl = (b * DZ_ + z) * HW_ + p0 + mt * 16 + g;
    const __half* Al = &g_O[(long long)rowl * E_];
    const __half* Ah = Al + 8LL * E_;

    float4 acc[8];
#pragma unroll
    for (int n = 0; n < 8; n++) acc[n] = make_float4(0.f, 0.f, 0.f, 0.f);

    for (int kb = 0; kb < 8; kb++) {
        __syncthreads();
        {
            int kk = tid & 31;
            int n0 = tid >> 5;
            for (int n = n0; n < 128; n += 8)
                bs[n * 33 + kk] = g_WpT[n * E_ + kb * 32 + kk];
        }
        __syncthreads();
#pragma unroll
        for (int kcl = 0; kcl < 4; kcl++) {
            int kcol = kb * 32 + kcl * 8;
            unsigned a0 = __float_as_uint(__half2float(Al[kcol + t]));
            unsigned a1 = __float_as_uint(__half2float(Ah[kcol + t]));
            unsigned a2 = __float_as_uint(__half2float(Al[kcol + t + 4]));
            unsigned a3 = __float_as_uint(__half2float(Ah[kcol + t + 4]));
#pragma unroll
            for (int n = 0; n < 8; n++) {
                const float* br = &bs[(nh * 64 + n * 8 + g) * 33 + kcl * 8];
                mma_tf32(acc[n], a0, a1, a2, a3,
                         __float_as_uint(br[t]), __float_as_uint(br[t + 4]));
            }
        }
    }
    __syncthreads();

    {
        int rl = mt * 16 + g;
#pragma unroll
        for (int n = 0; n < 8; n++) {
            int col = nh * 64 + n * 8 + 2 * t;
            s_o[col * 68 + rl] = acc[n].x;
            s_o[(col + 1) * 68 + rl] = acc[n].y;
            s_o[col * 68 + rl + 8] = acc[n].z;
            s_o[(col + 1) * 68 + rl + 8] = acc[n].w;
        }
    }
    __syncthreads();

    {
        int r = tid & 63;
        int cb = tid >> 6;
        for (int c = cb; c < C3_; c += 4) {
            long long oi = (long long)(b * C3_ + c) * (DZ_ * HW_) + z * HW_ + p0 + r;
            out[oi] = F3[oi] + s_o[c * 68 + r];
        }
    }
}

// ----------------------------------- launch ---------------------------------
extern "C" void kernel_launch(void* const* d_in, const int* in_sizes, int n_in,
                              void* d_out, int out_size) {
    const float* F3  = (const float*)d_in[0];
    const float* F2  = (const float*)d_in[1];
    const float* Wq  = (const float*)d_in[2];
    const float* Wk  = (const float*)d_in[3];
    const float* Wv  = (const float*)d_in[4];
    const float* Wp  = (const float*)d_in[5];
    const float* lnqg = (const float*)d_in[6];
    const float* lnqb = (const float*)d_in[7];
    const float* lnkg = (const float*)d_in[8];
    const float* lnkb = (const float*)d_in[9];
    const float* w1   = (const float*)d_in[10];
    const float* bng  = (const float*)d_in[11];
    const float* bnb  = (const float*)d_in[12];
    const float* w2   = (const float*)d_in[13];
    const float* w2b  = (const float*)d_in[14];
    const float* lam  = (const float*)d_in[15];
    const void*  D0p  = d_in[16];
    const void*  slabp = d_in[17];
    float* out = (float*)d_out;

    int front_smem = (128 * 72 + 256 * 33) * (int)sizeof(float);    // 70656 (qproj max)
    int attn_smem  = 256 * BST * (int)sizeof(__nv_bfloat16);        // 36864
    int oproj_smem = (128 * 33 + 128 * 68) * (int)sizeof(float);    // 51712
    static int cfg_done = 0;
    if (!cfg_done) {
        cudaFuncSetAttribute(k_front, cudaFuncAttributeMaxDynamicSharedMemorySize, front_smem);
        cudaFuncSetAttribute(k_attn, cudaFuncAttributeMaxDynamicSharedMemorySize, attn_smem);
        cudaFuncSetAttribute(k_oproj, cudaFuncAttributeMaxDynamicSharedMemorySize, oproj_smem);
        cfg_done = 1;
    }

    k_wprep<<<(TOPO_ * C2_ * 9 + 255) / 256, 256>>>(w1, Wq, Wp, Wk, Wv);
    k_front<<<NJ_CONV + NJ_Q + NJ_KV, 256, front_smem>>>(F2, F3, bng, bnb,
                                                         lnkg, lnkb, lnqg, lnqb);
    k_topo<<<B_ * K_, 192>>>(w2, w2b);
    k_attn<<<B_ * NH_ * (DZ_ / 2) * 9, 128, attn_smem>>>(lam, D0p, slabp);
    k_oproj<<<B_ * DZ_ * 9, 256, oproj_smem>>>(F3, out);
}

// round 17
// speedup vs baseline: 1.7168x; 1.1015x over previous
#include <cuda_runtime.h>
#include <cuda_bf16.h>
#include <cuda_fp16.h>
#include <math.h>

#define B_ 2
#define C3_ 128
#define DZ_ 32
#define HW_ 576
#define C2_ 96
#define K_ 8
#define E_ 256
#define NH_ 4
#define HD_ 64
#define TOPO_ 64
#define LN_EPS 1e-5f
#define LOG2E_ 1.4426950408889634f
#define ONESH 0x3C003C00u   // fp16 {1.0, 1.0}

// ------------------------- device scratch (no allocation) -------------------
__device__ float g_w1t[C2_ * 9 * TOPO_];
__device__ float g_h[B_ * K_ * HW_ * TOPO_];
__device__ float g_topo[B_ * K_ * HW_];
__device__ __nv_bfloat16 g_Q[B_ * NH_ * DZ_ * HW_ * HD_];   // pre-scaled by log2e/8
__device__ __nv_bfloat16 g_K[B_ * NH_ * K_ * HW_ * HD_];    // (b,h,c,p,d)
__device__ __half g_Vt[B_ * NH_ * K_ * HD_ * HW_];          // (b,h,c,d,p) fp16, transposed
__device__ __half g_O[B_ * DZ_ * HW_ * E_];                 // fp16 attention output
__device__ float g_WqT[E_ * C3_];
__device__ __half g_WpTh[C3_ * E_];                         // WpT fp16 (oproj B)
__device__ float g_WkT[E_ * C2_];
__device__ float g_WvT[E_ * C2_];

__device__ __forceinline__ int flex_int(const void* p, int dflt) {
    int v = *(const int*)p;
    if (v >= 1 && v <= 1000000) return v;
    float f = *(const float*)p;
    if (f >= 1.f && f <= 1000000.f) return (int)f;
    return dflt;
}

__device__ __forceinline__ unsigned pk2(float lo, float hi) {          // bf16x2
    unsigned r;
    asm("cvt.rn.bf16x2.f32 %0, %1, %2;" : "=r"(r) : "f"(hi), "f"(lo));
    return r;
}

__device__ __forceinline__ unsigned pkh(float lo, float hi) {          // f16x2
    unsigned r;
    asm("cvt.rn.f16x2.f32 %0, %1, %2;" : "=r"(r) : "f"(hi), "f"(lo));
    return r;
}

__device__ __forceinline__ unsigned ex2h(unsigned x) {                 // exp2 on f16x2
    unsigned y;
    asm("ex2.approx.f16x2 %0, %1;" : "=r"(y) : "r"(x));
    return y;
}

__device__ __forceinline__ void ldsm4(unsigned& r0, unsigned& r1,
                                      unsigned& r2, unsigned& r3, unsigned addr) {
    asm volatile("ldmatrix.sync.aligned.m8n8.x4.shared.b16 {%0,%1,%2,%3}, [%4];"
                 : "=r"(r0), "=r"(r1), "=r"(r2), "=r"(r3) : "r"(addr));
}

__device__ __forceinline__ void mma_tf32(float4& d,
                                         unsigned a0, unsigned a1, unsigned a2, unsigned a3,
                                         unsigned b0, unsigned b1) {
    asm volatile(
        "mma.sync.aligned.m16n8k8.row.col.f32.tf32.tf32.f32 "
        "{%0,%1,%2,%3}, {%4,%5,%6,%7}, {%8,%9}, {%0,%1,%2,%3};"
        : "+f"(d.x), "+f"(d.y), "+f"(d.z), "+f"(d.w)
        : "r"(a0), "r"(a1), "r"(a2), "r"(a3), "r"(b0), "r"(b1));
}

__device__ __forceinline__ void mma_bf16(float4& d,
                                         unsigned a0, unsigned a1, unsigned a2, unsigned a3,
                                         unsigned b0, unsigned b1) {
    asm volatile(
        "mma.sync.aligned.m16n8k16.row.col.f32.bf16.bf16.f32 "
        "{%0,%1,%2,%3}, {%4,%5,%6,%7}, {%8,%9}, {%0,%1,%2,%3};"
        : "+f"(d.x), "+f"(d.y), "+f"(d.z), "+f"(d.w)
        : "r"(a0), "r"(a1), "r"(a2), "r"(a3), "r"(b0), "r"(b1));
}

__device__ __forceinline__ void mma_f16(float4& d,
                                        unsigned a0, unsigned a1, unsigned a2, unsigned a3,
                                        unsigned b0, unsigned b1) {
    asm volatile(
        "mma.sync.aligned.m16n8k16.row.col.f32.f16.f16.f32 "
        "{%0,%1,%2,%3}, {%4,%5,%6,%7}, {%8,%9}, {%0,%1,%2,%3};"
        : "+f"(d.x), "+f"(d.y), "+f"(d.z), "+f"(d.w)
        : "r"(a0), "r"(a1), "r"(a2), "r"(a3), "r"(b0), "r"(b1));
}

// ------------------------- kernel 0: all weight prep ------------------------
__global__ void k_wprep(const float* __restrict__ w1,
                        const float* __restrict__ Wq, const float* __restrict__ Wp,
                        const float* __restrict__ Wk, const float* __restrict__ Wv) {
    int i = blockIdx.x * 256 + threadIdx.x;
    if (i < TOPO_ * C2_ * 9) {
        int o = i / (C2_ * 9);
        int r = i % (C2_ * 9);
        int c = r / 9, tap = r % 9;
        g_w1t[(c * 9 + tap) * TOPO_ + o] = w1[i];
    }
    if (i < C3_ * E_) {
        int e = i / C3_, c = i % C3_;
        g_WqT[i] = Wq[c * E_ + e];
        g_WpTh[c * E_ + e] = __float2half(Wp[i]);
    }
    if (i < C2_ * E_) {
        int e = i / C2_, c = i % C2_;
        g_WkT[i] = Wk[c * E_ + e];
        g_WvT[i] = Wv[c * E_ + e];
    }
}

// ===================== fused front: conv1 | qproj | kvproj ==================
__device__ void conv1_body(int job, const float* __restrict__ F2,
                           const float* __restrict__ bng,
                           const float* __restrict__ bnb, float* sm) {
    float* in_s = sm;            // [16][6][26]
    float* w_s = sm + 2496;      // [16*9*64]
    int bk = job / 6;
    int y0 = (job % 6) * 4;
    int b = bk >> 3, k = bk & 7;
    int tid = threadIdx.x;
    int pg = tid >> 3;
    int og = tid & 7;
    int pl = pg * 3;
    int yrel = pl / 24;
    int x0 = pl % 24;
    int o0 = og * 8;
    float acc[3][8];
#pragma unroll
    for (int u = 0; u < 3; u++)
#pragma unroll
        for (int v = 0; v < 8; v++) acc[u][v] = 0.f;

    for (int c0 = 0; c0 < C2_; c0 += 16) {
        __syncthreads();
        for (int idx = tid; idx < 16 * 6 * 26; idx += 256) {
            int cc = idx / 156, rem = idx % 156;
            int yy = rem / 26, xx = rem % 26;
            int y = y0 - 1 + yy, x = xx - 1;
            float v = 0.f;
            if ((unsigned)y < 24u && (unsigned)x < 24u)
                v = F2[((b * C2_ + c0 + cc) * HW_ + y * 24 + x) * K_ + k];
            in_s[cc * 156 + yy * 26 + xx] = v;
        }
        for (int idx = tid; idx < 16 * 9 * 64; idx += 256)
            w_s[idx] = g_w1t[c0 * 9 * 64 + idx];
        __syncthreads();
        for (int cc = 0; cc < 16; cc++) {
#pragma unroll
            for (int dy = 0; dy < 3; dy++) {
                float rv[5];
#pragma unroll
                for (int u = 0; u < 5; u++) rv[u] = in_s[cc * 156 + (yrel + dy) * 26 + x0 + u];
#pragma unroll
                for (int dx = 0; dx < 3; dx++) {
                    const float* wp = &w_s[(cc * 9 + dy * 3 + dx) * 64 + o0];
                    float4 wa = *(const float4*)wp;
                    float4 wb = *(const float4*)(wp + 4);
#pragma unroll
                    for (int u = 0; u < 3; u++) {
                        float a = rv[u + dx];
                        acc[u][0] += a * wa.x; acc[u][1] += a * wa.y;
                        acc[u][2] += a * wa.z; acc[u][3] += a * wa.w;
                        acc[u][4] += a * wb.x; acc[u][5] += a * wb.y;
                        acc[u][6] += a * wb.z; acc[u][7] += a * wb.w;
                    }
                }
            }
        }
    }
    float invs = rsqrtf(1.f + LN_EPS);
    float sg[8], sb[8];
#pragma unroll
    for (int v = 0; v < 8; v++) { sg[v] = bng[o0 + v] * invs; sb[v] = bnb[o0 + v]; }
#pragma unroll
    for (int u = 0; u < 3; u++) {
        int p = (y0 + yrel) * 24 + x0 + u;
        float4 h0, h1;
        h0.x = fmaxf(acc[u][0] * sg[0] + sb[0], 0.f);
        h0.y = fmaxf(acc[u][1] * sg[1] + sb[1], 0.f);
        h0.z = fmaxf(acc[u][2] * sg[2] + sb[2], 0.f);
        h0.w = fmaxf(acc[u][3] * sg[3] + sb[3], 0.f);
        h1.x = fmaxf(acc[u][4] * sg[4] + sb[4], 0.f);
        h1.y = fmaxf(acc[u][5] * sg[5] + sb[5], 0.f);
        h1.z = fmaxf(acc[u][6] * sg[6] + sb[6], 0.f);
        h1.w = fmaxf(acc[u][7] * sg[7] + sb[7], 0.f);
        *(float4*)&g_h[(bk * HW_ + p) * TOPO_ + o0] = h0;
        *(float4*)&g_h[(bk * HW_ + p) * TOPO_ + o0 + 4] = h1;
    }
}

__device__ void qproj_body(int job, const float* __restrict__ F3,
                           const float* __restrict__ lng,
                           const float* __restrict__ lnb, float* qsm) {
    float* xk = qsm;                  // [128][72]
    float* bs = qsm + 128 * 72;       // [256][33]
    float* s_o = qsm;                 // alias, [64][260]
    __shared__ float smean[64], srstd[64];

    int p0 = (job % 9) * 64;
    int z = (job / 9) % DZ_;
    int b = job / (9 * DZ_);

    int tid = threadIdx.x;
    int w = tid >> 5, lane = tid & 31;
    int g = lane >> 2, t = lane & 3;
    int mt = w & 3, nh = w >> 2;

    {
        int r = tid & 63;
        int cb = tid >> 6;
        for (int c = cb; c < C3_; c += 4)
            xk[c * 72 + r] = F3[(b * C3_ + c) * (DZ_ * HW_) + z * HW_ + p0 + r];
    }

    float4 acc[16];
#pragma unroll
    for (int n = 0; n < 16; n++) acc[n] = make_float4(0.f, 0.f, 0.f, 0.f);

    for (int kb = 0; kb < 4; kb++) {
        __syncthreads();
        {
            int kk = tid & 31;
            int n0 = tid >> 5;
            for (int n = n0; n < 256; n += 8)
                bs[n * 33 + kk] = g_WqT[n * C3_ + kb * 32 + kk];
        }
        __syncthreads();
#pragma unroll
        for (int kcl = 0; kcl < 4; kcl++) {
            int krow = kb * 32 + kcl * 8;
            int arow = mt * 16 + g;
            unsigned a0 = __float_as_uint(xk[(krow + t) * 72 + arow]);
            unsigned a1 = __float_as_uint(xk[(krow + t) * 72 + arow + 8]);
            unsigned a2 = __float_as_uint(xk[(krow + t + 4) * 72 + arow]);
            unsigned a3 = __float_as_uint(xk[(krow + t + 4) * 72 + arow + 8]);
#pragma unroll
            for (int n = 0; n < 16; n++) {
                const float* br = &bs[(nh * 128 + n * 8 + g) * 33 + kcl * 8];
                mma_tf32(acc[n], a0, a1, a2, a3,
                         __float_as_uint(br[t]), __float_as_uint(br[t + 4]));
            }
        }
    }
    __syncthreads();

    {
        int rl = mt * 16 + g;
#pragma unroll
        for (int n = 0; n < 16; n++) {
            int col = nh * 128 + n * 8 + 2 * t;
            s_o[rl * 260 + col] = acc[n].x;
            s_o[rl * 260 + col + 1] = acc[n].y;
            s_o[(rl + 8) * 260 + col] = acc[n].z;
            s_o[(rl + 8) * 260 + col + 1] = acc[n].w;
        }
    }
    __syncthreads();

#pragma unroll
    for (int rr = 0; rr < 8; rr++) {
        int row = w * 8 + rr;
        float s = 0.f, q = 0.f;
#pragma unroll
        for (int jj = 0; jj < 8; jj++) {
            float v = s_o[row * 260 + lane + 32 * jj];
            s += v; q += v * v;
        }
#pragma unroll
        for (int off = 16; off >= 1; off >>= 1) {
            s += __shfl_xor_sync(0xffffffffu, s, off);
            q += __shfl_xor_sync(0xffffffffu, q, off);
        }
        if (lane == 0) {
            float mu = s * (1.f / 256.f);
            smean[row] = mu;
            srstd[row] = rsqrtf(q * (1.f / 256.f) - mu * mu + LN_EPS);
        }
    }
    __syncthreads();

    {
        int cl = (tid & 63) * 4;
        int rb = tid >> 6;
        float4 g4 = *(const float4*)&lng[cl];
        float4 b4 = *(const float4*)&lnb[cl];
        int h = cl >> 6, cc = cl & 63;
        const float qscale = 0.125f * LOG2E_;
        long long obase = ((long long)(b * NH_ + h) * DZ_ + z) * HW_;
        for (int r = rb; r < 64; r += 4) {
            float mu = smean[r], rs = srstd[r];
            float v0 = ((s_o[r * 260 + cl] - mu) * rs * g4.x + b4.x) * qscale;
            float v1 = ((s_o[r * 260 + cl + 1] - mu) * rs * g4.y + b4.y) * qscale;
            float v2 = ((s_o[r * 260 + cl + 2] - mu) * rs * g4.z + b4.z) * qscale;
            float v3 = ((s_o[r * 260 + cl + 3] - mu) * rs * g4.w + b4.w) * qscale;
            uint2 u = make_uint2(pk2(v0, v1), pk2(v2, v3));
            *(uint2*)&g_Q[(obase + p0 + r) * HD_ + cc] = u;
        }
    }
}

__device__ void kvproj_body(int job, const float* __restrict__ F2,
                            const float* __restrict__ lng,
                            const float* __restrict__ lnb, float* ksm) {
    float* xk = ksm;                  // [96][72]
    float* bs = ksm + 96 * 72;        // [256][33]
    float* s_o = ksm;                 // alias at base (xk/bs dead post-mma)
    __shared__ float smean[64], srstd[64];

    int mat = job & 1;
    int sp = job >> 1;
    int p0 = (sp % 9) * 64;
    int k = (sp / 9) % K_;
    int b = sp / (9 * K_);

    int tid = threadIdx.x;
    int w = tid >> 5, lane = tid & 31;
    int g = lane >> 2, t = lane & 3;
    int mt = w & 3, nh = w >> 2;

    {
        int r = tid & 63;
        int cb = tid >> 6;
        for (int c = cb; c < C2_; c += 4)
            xk[c * 72 + r] = F2[((b * C2_ + c) * HW_ + p0 + r) * K_ + k];
    }

    const float* WT = mat == 0 ? g_WkT : g_WvT;
    float4 acc[16];
#pragma unroll
    for (int n = 0; n < 16; n++) acc[n] = make_float4(0.f, 0.f, 0.f, 0.f);

    for (int kb = 0; kb < 3; kb++) {
        __syncthreads();
        {
            int kk = tid & 31;
            int n0 = tid >> 5;
            for (int n = n0; n < 256; n += 8)
                bs[n * 33 + kk] = WT[n * C2_ + kb * 32 + kk];
        }
        __syncthreads();
#pragma unroll
        for (int kcl = 0; kcl < 4; kcl++) {
            int krow = kb * 32 + kcl * 8;
            int arow = mt * 16 + g;
            unsigned a0 = __float_as_uint(xk[(krow + t) * 72 + arow]);
            unsigned a1 = __float_as_uint(xk[(krow + t) * 72 + arow + 8]);
            unsigned a2 = __float_as_uint(xk[(krow + t + 4) * 72 + arow]);
            unsigned a3 = __float_as_uint(xk[(krow + t + 4) * 72 + arow + 8]);
#pragma unroll
            for (int n = 0; n < 16; n++) {
                const float* br = &bs[(nh * 128 + n * 8 + g) * 33 + kcl * 8];
                mma_tf32(acc[n], a0, a1, a2, a3,
                         __float_as_uint(br[t]), __float_as_uint(br[t + 4]));
            }
        }
    }
    __syncthreads();
    {
        int rl = mt * 16 + g;
#pragma unroll
        for (int n = 0; n < 16; n++) {
            int col = nh * 128 + n * 8 + 2 * t;
            s_o[rl * 260 + col] = acc[n].x;
            s_o[rl * 260 + col + 1] = acc[n].y;
            s_o[(rl + 8) * 260 + col] = acc[n].z;
            s_o[(rl + 8) * 260 + col + 1] = acc[n].w;
        }
    }
    __syncthreads();
#pragma unroll
    for (int rr = 0; rr < 8; rr++) {
        int row = w * 8 + rr;
        float s = 0.f, q = 0.f;
#pragma unroll
        for (int jj = 0; jj < 8; jj++) {
            float v = s_o[row * 260 + lane + 32 * jj];
            s += v; q += v * v;
        }
#pragma unroll
        for (int off = 16; off >= 1; off >>= 1) {
            s += __shfl_xor_sync(0xffffffffu, s, off);
            q += __shfl_xor_sync(0xffffffffu, q, off);
        }
        if (lane == 0) {
            float mu = s * (1.f / 256.f);
            smean[row] = mu;
            srstd[row] = rsqrtf(q * (1.f / 256.f) - mu * mu + LN_EPS);
        }
    }
    __syncthreads();

    if (mat == 0) {
        int cl = (tid & 63) * 4;
        int rb = tid >> 6;
        float4 g4 = *(const float4*)&lng[cl];
        float4 b4 = *(const float4*)&lnb[cl];
        int h = cl >> 6, cc = cl & 63;
        long long obase = ((long long)(b * NH_ + h) * K_ + k) * HW_;
        for (int r = rb; r < 64; r += 4) {
            float mu = smean[r], rs = srstd[r];
            float v0 = (s_o[r * 260 + cl] - mu) * rs * g4.x + b4.x;
            float v1 = (s_o[r * 260 + cl + 1] - mu) * rs * g4.y + b4.y;
            float v2 = (s_o[r * 260 + cl + 2] - mu) * rs * g4.z + b4.z;
            float v3 = (s_o[r * 260 + cl + 3] - mu) * rs * g4.w + b4.w;
            uint2 u = make_uint2(pk2(v0, v1), pk2(v2, v3));
            *(uint2*)&g_K[(obase + p0 + r) * HD_ + cc] = u;
        }
    } else {
        int e = tid;
        float ge = lng[e], be = lnb[e];
        int h = e >> 6, d = e & 63;
        long long vb = (((long long)(b * NH_ + h) * K_ + k) * HD_ + d) * HW_ + p0;
#pragma unroll
        for (int rb2 = 0; rb2 < 16; rb2++) {
            int r = rb2 * 4;
            float v0 = (s_o[r * 260 + e] - smean[r]) * srstd[r] * ge + be;
            float v1 = (s_o[(r + 1) * 260 + e] - smean[r + 1]) * srstd[r + 1] * ge + be;
            float v2 = (s_o[(r + 2) * 260 + e] - smean[r + 2]) * srstd[r + 2] * ge + be;
            float v3 = (s_o[(r + 3) * 260 + e] - smean[r + 3]) * srstd[r + 3] * ge + be;
            uint2 u = make_uint2(pkh(v0, v1), pkh(v2, v3));   // fp16 V
            *(uint2*)&g_Vt[vb + r] = u;
        }
    }
}

#define NJ_CONV 96
#define NJ_Q 576
#define NJ_KV 288
__global__ __launch_bounds__(256) void k_front(const float* __restrict__ F2,
                                               const float* __restrict__ F3,
                                               const float* __restrict__ bng,
                                               const float* __restrict__ bnb,
                                               const float* __restrict__ lnkg,
                                               const float* __restrict__ lnkb,
                                               const float* __restrict__ lnqg,
                                               const float* __restrict__ lnqb) {
    extern __shared__ float fsm[];
    int job = blockIdx.x;
    if (job < NJ_CONV) {
        conv1_body(job, F2, bng, bnb, fsm);
    } else if (job < NJ_CONV + NJ_Q) {
        qproj_body(job - NJ_CONV, F3, lnqg, lnqb, fsm);
    } else {
        kvproj_body(job - NJ_CONV - NJ_Q, F2, lnkg, lnkb, fsm);
    }
}

// ------------------- kernel 2: conv2 1x1 + neighbor-sum -> topo -------------
__global__ __launch_bounds__(192) void k_topo(const float* __restrict__ w2,
                                              const float* __restrict__ w2b) {
    __shared__ float sp[HW_];
    __shared__ float wsh[64];
    int bk = blockIdx.x;
    int tid = threadIdx.x;
    if (tid < 64) wsh[tid] = w2[tid];
    __syncthreads();
    for (int p = tid; p < HW_; p += 192) {
        const float* hp = &g_h[(bk * HW_ + p) * TOPO_];
        float s = w2b[0];
#pragma unroll
        for (int o = 0; o < 64; o += 4) {
            float4 hv = *(const float4*)&hp[o];
            s += hv.x * wsh[o] + hv.y * wsh[o + 1] + hv.z * wsh[o + 2] + hv.w * wsh[o + 3];
        }
        sp[p] = s;
    }
    __syncthreads();
    for (int p = tid; p < HW_; p += 192) {
        int y = p / 24, x = p % 24;
        float s = 0.f;
#pragma unroll
        for (int dy = -1; dy <= 1; dy++)
#pragma unroll
            for (int dx = -1; dx <= 1; dx++) {
                if (dy == 0 && dx == 0) continue;
                int yy = y + dy, xx = x + dx;
                if ((unsigned)yy < 24u && (unsigned)xx < 24u) s += sp[yy * 24 + xx];
            }
        g_topo[bk * HW_ + p] = sp[p] + 0.5f * s;
    }
}

// ------ kernel 5: flash attention (bf16 S-mma, f16x2 exp, f16 PV-mma) -------
// Locked best configuration: 128 threads, 2 z/block, 64-key tiles, BST=72.
#define BST 72
__global__ __launch_bounds__(128) void k_attn(const float* __restrict__ lam_p,
                                              const void* __restrict__ D0_p,
                                              const void* __restrict__ slab_p) {
    extern __shared__ __nv_bfloat16 bsm[];
    __nv_bfloat16* Qs = bsm;                   // [128][BST]
    __nv_bfloat16* Ks = bsm + 128 * BST;       // [64][BST]
    __half* Vs = (__half*)(bsm + 192 * BST);   // [64][BST] fp16

    int bid = blockIdx.x;
    int p0 = (bid % 9) * 64;
    int zp = (bid / 9) % (DZ_ / 2);
    int h = (bid / (9 * (DZ_ / 2))) % NH_;
    int b = bid / (9 * (DZ_ / 2) * NH_);
    int z0 = zp * 2;

    int D0 = flex_int(D0_p, 128);
    int slab = flex_int(slab_p, 16);
    float lam2 = (*lam_p) * LOG2E_;

    int kkz[2], cloz[2], chiz[2];
#pragma unroll
    for (int i = 0; i < 2; i++) {
        int zz = z0 + i;
        int zq = (int)llrint((double)(D0 - 1) * (double)zz / (double)(DZ_ - 1));
        int kk = zq / slab;
        if (kk < 0) kk = 0;
        if (kk > K_ - 1) kk = K_ - 1;
        kkz[i] = kk;
        cloz[i] = (kk - 1 < 0) ? 0 : kk - 1;
        chiz[i] = (kk + 1 > K_ - 1) ? K_ - 1 : kk + 1;
    }
    int cU_lo = min(cloz[0], cloz[1]);
    int cU_hi = max(chiz[0], chiz[1]);

    int tid = threadIdx.x;
    int w = tid >> 5;
    int lane = tid & 31;
    int g = lane >> 2;
    int t = lane & 3;

    int wz = w >> 1;
    int zw = z0 + wz;
    int kk_w = kkz[wz], clo_w = cloz[wz], chi_w = chiz[wz];
    int prow = p0 + (w & 1) * 32;
    int qrow = w * 32;

    unsigned qb_s = (unsigned)__cvta_generic_to_shared(Qs);
    unsigned kb_s = (unsigned)__cvta_generic_to_shared(Ks);
    unsigned vb_s = (unsigned)__cvta_generic_to_shared(Vs);
    unsigned laneoff = (((lane & 7) + ((lane >> 3) & 1) * 8) * BST + ((lane >> 4) & 1) * 8) * 2;

    {
        long long qb0 = ((((long long)(b * NH_ + h) * DZ_ + z0) * HW_) + p0) * HD_;
#pragma unroll
        for (int it = 0; it < 8; it++) {
            int idx = tid + it * 128;
            int r = idx >> 3, v = (idx & 7) * 8;
            long long src = qb0 + (long long)(r >> 6) * (HW_ * HD_) + (long long)(r & 63) * 64 + v;
            *(uint4*)&Qs[r * BST + v] = *(const uint4*)&g_Q[src];
        }
    }

    float4 lacc0 = make_float4(0.f, 0.f, 0.f, 0.f);
    float4 lacc1 = make_float4(0.f, 0.f, 0.f, 0.f);
    float4 O0[8], O1[8];
#pragma unroll
    for (int n = 0; n < 8; n++) {
        O0[n] = make_float4(0.f, 0.f, 0.f, 0.f);
        O1[n] = make_float4(0.f, 0.f, 0.f, 0.f);
    }

    for (int c = cU_lo; c <= cU_hi; c++) {
        bool active = (c >= clo_w) && (c <= chi_w);
        float bias2 = (c == kk_w) ? 0.f : -0.5f * LOG2E_;
        long long kb = (((long long)(b * NH_ + h) * K_ + c) * HW_) * HD_;
        long long vb = (((long long)(b * NH_ + h) * K_ + c) * HD_) * HW_;
        const float* topo_c = &g_topo[(b * K_ + c) * HW_];
        for (int pk0 = 0; pk0 < HW_; pk0 += 64) {
            __syncthreads();
#pragma unroll
            for (int it = 0; it < 4; it++) {
                int idx = tid + it * 128;
                int r = idx >> 3, v = (idx & 7) * 8;
                *(uint4*)&Ks[r * BST + v] = *(const uint4*)&g_K[kb + (long long)(pk0 + r) * 64 + v];
                *(uint4*)&Vs[r * BST + v] = *(const uint4*)&g_Vt[vb + (long long)r * HW_ + pk0 + v];
            }
            __syncthreads();
            if (!active) continue;

            // ---- S = Q*K^T (bf16) ----
            float4 S0[8], S1[8];
#pragma unroll
            for (int n = 0; n < 8; n++) {
                S0[n] = make_float4(0.f, 0.f, 0.f, 0.f);
                S1[n] = make_float4(0.f, 0.f, 0.f, 0.f);
            }
#pragma unroll
            for (int kc = 0; kc < 4; kc++) {
                int kc16 = kc * 16;
                unsigned a00, a01, a02, a03, a10, a11, a12, a13;
                ldsm4(a00, a01, a02, a03, qb_s + (qrow * BST + kc16) * 2 + laneoff);
                ldsm4(a10, a11, a12, a13, qb_s + ((qrow + 16) * BST + kc16) * 2 + laneoff);
#pragma unroll
                for (int n2 = 0; n2 < 4; n2++) {
                    unsigned b0, b1, b2, b3;
                    ldsm4(b0, b1, b2, b3, kb_s + ((n2 * 16) * BST + kc16) * 2 + laneoff);
                    mma_bf16(S0[2 * n2],     a00, a01, a02, a03, b0, b2);
                    mma_bf16(S0[2 * n2 + 1], a00, a01, a02, a03, b1, b3);
                    mma_bf16(S1[2 * n2],     a10, a11, a12, a13, b0, b2);
                    mma_bf16(S1[2 * n2 + 1], a10, a11, a12, a13, b1, b3);
                }
            }

            // ---- bias (+ diagonal topo only when pixel tiles coincide) ----
            if (pk0 == p0) {
                int rq0 = prow + g;
                int rq1 = prow + 16 + g;
#pragma unroll
                for (int n = 0; n < 8; n++) {
                    int j0 = pk0 + n * 8 + 2 * t;
                    int j1 = j0 + 1;
                    float d00 = bias2, d01 = bias2, d02 = bias2, d03 = bias2;
                    float d10 = bias2, d11 = bias2, d12 = bias2, d13 = bias2;
                    if (rq0 == j0)     d00 += lam2 * topo_c[j0];
                    if (rq0 == j1)     d01 += lam2 * topo_c[j1];
                    if (rq0 + 8 == j0) d02 += lam2 * topo_c[j0];
                    if (rq0 + 8 == j1) d03 += lam2 * topo_c[j1];
                    if (rq1 == j0)     d10 += lam2 * topo_c[j0];
                    if (rq1 == j1)     d11 += lam2 * topo_c[j1];
                    if (rq1 + 8 == j0) d12 += lam2 * topo_c[j0];
                    if (rq1 + 8 == j1) d13 += lam2 * topo_c[j1];
                    S0[n].x += d00; S0[n].y += d01; S0[n].z += d02; S0[n].w += d03;
                    S1[n].x += d10; S1[n].y += d11; S1[n].z += d12; S1[n].w += d13;
                }
            } else {
#pragma unroll
                for (int n = 0; n < 8; n++) {
                    S0[n].x += bias2; S0[n].y += bias2; S0[n].z += bias2; S0[n].w += bias2;
                    S1[n].x += bias2; S1[n].y += bias2; S1[n].z += bias2; S1[n].w += bias2;
                }
            }

            // ---- P = exp2(S) in packed fp16; O += P*V; l via ones-mma ----
#pragma unroll
            for (int kc = 0; kc < 4; kc++) {
                int kc16 = kc * 16;
                unsigned a00 = ex2h(pkh(S0[2 * kc].x, S0[2 * kc].y));
                unsigned a01 = ex2h(pkh(S0[2 * kc].z, S0[2 * kc].w));
                unsigned a02 = ex2h(pkh(S0[2 * kc + 1].x, S0[2 * kc + 1].y));
                unsigned a03 = ex2h(pkh(S0[2 * kc + 1].z, S0[2 * kc + 1].w));
                unsigned a10 = ex2h(pkh(S1[2 * kc].x, S1[2 * kc].y));
                unsigned a11 = ex2h(pkh(S1[2 * kc].z, S1[2 * kc].w));
                unsigned a12 = ex2h(pkh(S1[2 * kc + 1].x, S1[2 * kc + 1].y));
                unsigned a13 = ex2h(pkh(S1[2 * kc + 1].z, S1[2 * kc + 1].w));
                mma_f16(lacc0, a00, a01, a02, a03, ONESH, ONESH);
                mma_f16(lacc1, a10, a11, a12, a13, ONESH, ONESH);
#pragma unroll
                for (int n2 = 0; n2 < 4; n2++) {
                    unsigned b0, b1, b2, b3;
                    ldsm4(b0, b1, b2, b3, vb_s + ((n2 * 16) * BST + kc16) * 2 + laneoff);
                    mma_f16(O0[2 * n2],     a00, a01, a02, a03, b0, b2);
                    mma_f16(O0[2 * n2 + 1], a00, a01, a02, a03, b1, b3);
                    mma_f16(O1[2 * n2],     a10, a11, a12, a13, b0, b2);
                    mma_f16(O1[2 * n2 + 1], a10, a11, a12, a13, b1, b3);
                }
            }
        }
    }

    float i00 = 1.f / lacc0.x, i01 = 1.f / lacc0.z;
    float i10 = 1.f / lacc1.x, i11 = 1.f / lacc1.z;
    long long ob = ((long long)(b * DZ_ + zw) * HW_) * E_ + h * HD_;
    int rq0 = prow + g, rq1 = prow + 16 + g;
#pragma unroll
    for (int n = 0; n < 8; n++) {
        int col = n * 8 + 2 * t;
        *(unsigned*)&g_O[ob + (long long)rq0 * E_ + col] = pkh(O0[n].x * i00, O0[n].y * i00);
        *(unsigned*)&g_O[ob + (long long)(rq0 + 8) * E_ + col] = pkh(O0[n].z * i01, O0[n].w * i01);
        *(unsigned*)&g_O[ob + (long long)rq1 * E_ + col] = pkh(O1[n].x * i10, O1[n].y * i10);
        *(unsigned*)&g_O[ob + (long long)(rq1 + 8) * E_ + col] = pkh(O1[n].z * i11, O1[n].w * i11);
    }
}

// ---- kernel 6: output projection + residual (fp16 m16n8k16 MMA) ------------
#define OBST 40   // fp16 B smem stride (halves)
__global__ __launch_bounds__(256) void k_oproj(const float* __restrict__ F3,
                                               float* __restrict__ out) {
    extern __shared__ float osm[];
    __half* bsh = (__half*)osm;       // [128][OBST] fp16 = 10240 B
    float* s_o = osm + 2560;          // [128 cols][68 rows] f32
    int bid = blockIdx.x;
    int p0 = (bid % 9) * 64;
    int z = (bid / 9) % DZ_;
    int b = bid / (9 * DZ_);

    int tid = threadIdx.x;
    int w = tid >> 5, lane = tid & 31;
    int g = lane >> 2, t = lane & 3;
    int mt = w & 3, nh = w >> 2;

    int rowl = (b * DZ_ + z) * HW_ + p0 + mt * 16 + g;
    const __half* Al = &g_O[(long long)rowl * E_];
    const __half* Ah = Al + 8LL * E_;

    float4 acc[8];
#pragma unroll
    for (int n = 0; n < 8; n++) acc[n] = make_float4(0.f, 0.f, 0.f, 0.f);

    for (int kb = 0; kb < 8; kb++) {
        __syncthreads();
        {
            int kk = tid & 31;
            int n0 = tid >> 5;
            for (int n = n0; n < 128; n += 8)
                bsh[n * OBST + kk] = g_WpTh[n * E_ + kb * 32 + kk];
        }
        __syncthreads();
#pragma unroll
        for (int kcl = 0; kcl < 2; kcl++) {
            int kcol = kb * 32 + kcl * 16;
            unsigned a0 = *(const unsigned*)&Al[kcol + 2 * t];
            unsigned a1 = *(const unsigned*)&Ah[kcol + 2 * t];
            unsigned a2 = *(const unsigned*)&Al[kcol + 8 + 2 * t];
            unsigned a3 = *(const unsigned*)&Ah[kcol + 8 + 2 * t];
#pragma unroll
            for (int n = 0; n < 8; n++) {
                const __half* br = &bsh[(nh * 64 + n * 8 + g) * OBST + kcl * 16];
                unsigned b0 = *(const unsigned*)&br[2 * t];
                unsigned b1 = *(const unsigned*)&br[2 * t + 8];
                mma_f16(acc[n], a0, a1, a2, a3, b0, b1);
            }
        }
    }
    __syncthreads();

    {
        int rl = mt * 16 + g;
#pragma unroll
        for (int n = 0; n < 8; n++) {
            int col = nh * 64 + n * 8 + 2 * t;
            s_o[col * 68 + rl] = acc[n].x;
            s_o[(col + 1) * 68 + rl] = acc[n].y;
            s_o[col * 68 + rl + 8] = acc[n].z;
            s_o[(col + 1) * 68 + rl + 8] = acc[n].w;
        }
    }
    __syncthreads();

    {
        int r = tid & 63;
        int cb = tid >> 6;
        for (int c = cb; c < C3_; c += 4) {
            long long oi = (long long)(b * C3_ + c) * (DZ_ * HW_) + z * HW_ + p0 + r;
            out[oi] = F3[oi] + s_o[c * 68 + r];
        }
    }
}

// ----------------------------------- launch ---------------------------------
extern "C" void kernel_launch(void* const* d_in, const int* in_sizes, int n_in,
                              void* d_out, int out_size) {
    const float* F3  = (const float*)d_in[0];
    const float* F2  = (const float*)d_in[1];
    const float* Wq  = (const float*)d_in[2];
    const float* Wk  = (const float*)d_in[3];
    const float* Wv  = (const float*)d_in[4];
    const float* Wp  = (const float*)d_in[5];
    const float* lnqg = (const float*)d_in[6];
    const float* lnqb = (const float*)d_in[7];
    const float* lnkg = (const float*)d_in[8];
    const float* lnkb = (const float*)d_in[9];
    const float* w1   = (const float*)d_in[10];
    const float* bng  = (const float*)d_in[11];
    const float* bnb  = (const float*)d_in[12];
    const float* w2   = (const float*)d_in[13];
    const float* w2b  = (const float*)d_in[14];
    const float* lam  = (const float*)d_in[15];
    const void*  D0p  = d_in[16];
    const void*  slabp = d_in[17];
    float* out = (float*)d_out;

    int front_smem = (128 * 72 + 256 * 33) * (int)sizeof(float);    // 70656 (qproj max)
    int attn_smem  = 256 * BST * (int)sizeof(__nv_bfloat16);        // 36864
    int oproj_smem = 2560 * 4 + 128 * 68 * 4;                       // 45056
    static int cfg_done = 0;
    if (!cfg_done) {
        cudaFuncSetAttribute(k_front, cudaFuncAttributeMaxDynamicSharedMemorySize, front_smem);
        cudaFuncSetAttribute(k_attn, cudaFuncAttributeMaxDynamicSharedMemorySize, attn_smem);
        cudaFuncSetAttribute(k_oproj, cudaFuncAttributeMaxDynamicSharedMemorySize, oproj_smem);
        cfg_done = 1;
    }

    k_wprep<<<(TOPO_ * C2_ * 9 + 255) / 256, 256>>>(w1, Wq, Wp, Wk, Wv);
    k_front<<<NJ_CONV + NJ_Q + NJ_KV, 256, front_smem>>>(F2, F3, bng, bnb,
                                                         lnkg, lnkb, lnqg, lnqb);
    k_topo<<<B_ * K_, 192>>>(w2, w2b);
    k_attn<<<B_ * NH_ * (DZ_ / 2) * 9, 128, attn_smem>>>(lam, D0p, slabp);
    k_oproj<<<B_ * DZ_ * 9, 256, oproj_smem>>>(F3, out);
}